// round 14
// baseline (speedup 1.0000x reference)
#include <cuda_runtime.h>
#include <cuda_fp16.h>
#include <math.h>
#include <stdint.h>

// ---------------------------------------------------------------------------
// Problem constants
// ---------------------------------------------------------------------------
#define BATCH   4
#define SEQ     2048
#define DMODEL  1024
#define NHEAD   16
#define DK      64
#define DFF     4096
#define NTOK    (BATCH * SEQ)          // 8192
#define LN_EPS  1e-5f
#define QLD     (3 * DMODEL)           // packed qkv row stride

// ---------------------------------------------------------------------------
// Scratch (device globals — allocation-free rule)
// ---------------------------------------------------------------------------
__device__ __half g_xh   [NTOK * DMODEL];
__device__ __half g_qkvh [NTOK * QLD];
__device__ __half g_ctxh [NTOK * DMODEL];
__device__ __half g_hrh  [NTOK * DMODEL];
__device__ __half g_ffh  [NTOK * DFF];
__device__ __half g_attnh[NTOK * DMODEL];
__device__ __half g_f2h  [NTOK * DMODEL];
__device__ float  g_h    [NTOK * DMODEL];
// fp16 ROW-MAJOR weights: wh[k][n] = (half)w[k][n]
__device__ __half g_wqkvh[DMODEL * QLD];
__device__ __half g_woh  [DMODEL * DMODEL];
__device__ __half g_w1h  [DMODEL * DFF];
__device__ __half g_w2h  [DFF * DMODEL];

// ---------------------------------------------------------------------------
// Helpers
// ---------------------------------------------------------------------------
__device__ __forceinline__ uint32_t smem_u32(const void* p) {
    return (uint32_t)__cvta_generic_to_shared(p);
}
__device__ __forceinline__ void cp_async16(uint32_t dst, const void* src) {
    asm volatile("cp.async.cg.shared.global [%0], [%1], 16;\n" :: "r"(dst), "l"(src));
}
__device__ __forceinline__ void cp_commit() { asm volatile("cp.async.commit_group;\n"); }
__device__ __forceinline__ void cp_wait0()  { asm volatile("cp.async.wait_group 0;\n"); }

// mma.m16n8k16 row.col f32 += f16 * f16  (attention)
__device__ __forceinline__ void mma_f16(float* c, const uint32_t* a,
                                        uint32_t b0, uint32_t b1) {
    asm volatile(
        "mma.sync.aligned.m16n8k16.row.col.f32.f16.f16.f32 "
        "{%0,%1,%2,%3}, {%4,%5,%6,%7}, {%8,%9}, {%0,%1,%2,%3};"
        : "+f"(c[0]), "+f"(c[1]), "+f"(c[2]), "+f"(c[3])
        : "r"(a[0]), "r"(a[1]), "r"(a[2]), "r"(a[3]), "r"(b0), "r"(b1));
}

// mma.m16n8k16 row.col f16 += f16 * f16  (GEMM mainloop; D/C packed half2)
// c[0] = (row g,   cols 2th, 2th+1) ; c[1] = (row g+8, cols 2th, 2th+1)
__device__ __forceinline__ void mma_f16acc(uint32_t* c, const uint32_t* a,
                                           uint32_t b0, uint32_t b1) {
    asm volatile(
        "mma.sync.aligned.m16n8k16.row.col.f16.f16.f16.f16 "
        "{%0,%1}, {%2,%3,%4,%5}, {%6,%7}, {%0,%1};"
        : "+r"(c[0]), "+r"(c[1])
        : "r"(a[0]), "r"(a[1]), "r"(a[2]), "r"(a[3]), "r"(b0), "r"(b1));
}

__device__ __forceinline__ void ldsm_x4(uint32_t* r, uint32_t addr) {
    asm volatile("ldmatrix.sync.aligned.m8n8.x4.shared.b16 {%0,%1,%2,%3}, [%4];"
                 : "=r"(r[0]), "=r"(r[1]), "=r"(r[2]), "=r"(r[3]) : "r"(addr));
}
__device__ __forceinline__ void ldsm_x4_trans(uint32_t* r, uint32_t addr) {
    asm volatile("ldmatrix.sync.aligned.m8n8.x4.trans.shared.b16 {%0,%1,%2,%3}, [%4];"
                 : "=r"(r[0]), "=r"(r[1]), "=r"(r[2]), "=r"(r[3]) : "r"(addr));
}

// ---------------------------------------------------------------------------
// Fused prep: one launch converts x + all weights to fp16 (qkv packed).
// ---------------------------------------------------------------------------
#define U_X   (NTOK * DMODEL / 4)
#define U_W   (DMODEL * DMODEL / 4)
#define U_F   (DMODEL * DFF / 4)
#define U_TOT (U_X + 4 * U_W + 2 * U_F)

__device__ __forceinline__ void cv_lin(const float* in, __half* out, int i) {
    float4 v = *(const float4*)(in + 4 * (size_t)i);
    *(__half2*)(out + 4 * (size_t)i)     = __floats2half2_rn(v.x, v.y);
    *(__half2*)(out + 4 * (size_t)i + 2) = __floats2half2_rn(v.z, v.w);
}
__device__ __forceinline__ void cv_pack(const float* in, __half* out, int i, int off) {
    int row = i >> 8, c4 = (i & 255) * 4;
    float4 v = *(const float4*)(in + (size_t)row * DMODEL + c4);
    __half* o = out + (size_t)row * QLD + off + c4;
    *(__half2*)o       = __floats2half2_rn(v.x, v.y);
    *(__half2*)(o + 2) = __floats2half2_rn(v.z, v.w);
}

__global__ __launch_bounds__(256)
void prep_all_kernel(const float* __restrict__ x,
                     const float* __restrict__ wq, const float* __restrict__ wk,
                     const float* __restrict__ wv, const float* __restrict__ wo,
                     const float* __restrict__ w1, const float* __restrict__ w2,
                     __half* __restrict__ xh, __half* __restrict__ wqkvh,
                     __half* __restrict__ woh, __half* __restrict__ w1h,
                     __half* __restrict__ w2h) {
    int i = blockIdx.x * blockDim.x + threadIdx.x;
    if (i >= U_TOT) return;
    if (i < U_X)            { cv_lin(x, xh, i); return; }
    i -= U_X;
    if (i < U_W)            { cv_pack(wq, wqkvh, i, 0);          return; }
    i -= U_W;
    if (i < U_W)            { cv_pack(wk, wqkvh, i, DMODEL);     return; }
    i -= U_W;
    if (i < U_W)            { cv_pack(wv, wqkvh, i, 2 * DMODEL); return; }
    i -= U_W;
    if (i < U_W)            { cv_lin(wo, woh, i); return; }
    i -= U_W;
    if (i < U_F)            { cv_lin(w1, w1h, i); return; }
    i -= U_F;
    cv_lin(w2, w2h, i);
}

// ---------------------------------------------------------------------------
// FP16 GEMM with FP16-ACCUMULATE mainloop (2x mma rate hypothesis).
// CTA tile 64x128, BK=64, 8 warps, warp tile 32x32. Within each K=64 chunk the
// 4 mmas chain in fp16 (hc); chunk result promoted into fp32 acc.
// 2-stage cp.async. C[M,N] = A[M,K] @ B[K,N] (+bias)(+relu).
// smem/stage: A 64x72 + B 64x136 halves = 26,624 B; 2 stages = 53,248 B.
// ---------------------------------------------------------------------------
#define HLD  72
#define BLD  136
#define HA_H (64 * HLD)
#define HB_H (64 * BLD)
#define HSTAGE_ALL (HA_H + HB_H)
#define HGEMM_SMEM (2 * HSTAGE_ALL * (int)sizeof(__half))

template<bool BIAS, bool RELU, bool HOUT>
__global__ __launch_bounds__(256, 3)
void hgemm(const __half* __restrict__ A, const __half* __restrict__ B,
           const float* __restrict__ bias, void* __restrict__ Cv,
           int M, int N, int K) {
    extern __shared__ __half hsm[];

    const int tid  = threadIdx.x;
    const int lane = tid & 31;
    const int warp = tid >> 5;
    const int wm   = warp & 1;        // 32-row half of 64
    const int wn   = warp >> 1;       // 32-col quarter of 128
    const int g    = lane >> 2;
    const int th   = lane & 3;
    const int lrow = lane & 7;
    const int lgrp = lane >> 3;

    const int rowBase = blockIdx.y * 64;
    const int colBase = blockIdx.x * 128;

    float acc[2][4][4];
#pragma unroll
    for (int i = 0; i < 2; i++)
#pragma unroll
        for (int j = 0; j < 4; j++)
#pragma unroll
            for (int r = 0; r < 4; r++) acc[i][j][r] = 0.f;

    uint32_t aoff[2], boff[2];
#pragma unroll
    for (int mt = 0; mt < 2; mt++)
        aoff[mt] = (uint32_t)(((wm * 32 + mt * 16 + (lgrp & 1) * 8 + lrow) * HLD
                               + (lgrp >> 1) * 8) * 2);
#pragma unroll
    for (int p = 0; p < 2; p++)
        boff[p] = (uint32_t)((((lgrp & 1) * 8 + lrow) * BLD
                              + wn * 32 + p * 16 + (lgrp >> 1) * 8) * 2
                             + HA_H * 2);

    auto load_chunk = [&](int c) {
        const int s = c & 1;
        __half* as = hsm + s * HSTAGE_ALL;
        __half* bs = as + HA_H;
        const size_t koff = (size_t)c * 64;
#pragma unroll
        for (int p = 0; p < 2; p++) {
            int idx = tid + p * 256;
            int ra = idx >> 3, ja = (idx & 7) * 8;
            cp_async16(smem_u32(as + ra * HLD + ja),
                       A + (size_t)(rowBase + ra) * K + koff + ja);
        }
#pragma unroll
        for (int p = 0; p < 4; p++) {
            int idx = tid + p * 256;
            int rb = idx >> 4, jb = (idx & 15) * 8;
            cp_async16(smem_u32(bs + rb * BLD + jb),
                       B + (koff + rb) * N + colBase + jb);
        }
        cp_commit();
    };

    const int nk = K / 64;
    load_chunk(0);

    for (int it = 0; it < nk; it++) {
        cp_wait0();
        __syncthreads();
        if (it + 1 < nk) load_chunk(it + 1);

        const uint32_t sbase = smem_u32(hsm + (it & 1) * HSTAGE_ALL);

        // fp16 accumulators for this K=64 chunk
        uint32_t hc[2][4][2];
#pragma unroll
        for (int mt = 0; mt < 2; mt++)
#pragma unroll
            for (int nt = 0; nt < 4; nt++) { hc[mt][nt][0] = 0u; hc[mt][nt][1] = 0u; }

#pragma unroll
        for (int ks = 0; ks < 4; ks++) {
            uint32_t af[2][4], bf[2][4];
#pragma unroll
            for (int mt = 0; mt < 2; mt++)
                ldsm_x4(af[mt], sbase + aoff[mt] + ks * 32);
#pragma unroll
            for (int p = 0; p < 2; p++)
                ldsm_x4_trans(bf[p], sbase + boff[p] + (uint32_t)(ks * 16 * BLD * 2));
#pragma unroll
            for (int mt = 0; mt < 2; mt++) {
                mma_f16acc(hc[mt][0], af[mt], bf[0][0], bf[0][1]);
                mma_f16acc(hc[mt][1], af[mt], bf[0][2], bf[0][3]);
                mma_f16acc(hc[mt][2], af[mt], bf[1][0], bf[1][1]);
                mma_f16acc(hc[mt][3], af[mt], bf[1][2], bf[1][3]);
            }
        }

        // promote chunk to fp32
#pragma unroll
        for (int mt = 0; mt < 2; mt++)
#pragma unroll
            for (int nt = 0; nt < 4; nt++) {
                float2 lo = __half22float2(*(__half2*)&hc[mt][nt][0]);
                float2 hi = __half22float2(*(__half2*)&hc[mt][nt][1]);
                acc[mt][nt][0] += lo.x; acc[mt][nt][1] += lo.y;
                acc[mt][nt][2] += hi.x; acc[mt][nt][3] += hi.y;
            }
    }

    float* Cf = (float*)Cv;
    __half* Ch = (__half*)Cv;
#pragma unroll
    for (int mt = 0; mt < 2; mt++) {
        const int r0 = rowBase + wm * 32 + mt * 16 + g;
#pragma unroll
        for (int nt = 0; nt < 4; nt++) {
            const int c0 = colBase + wn * 32 + nt * 8 + 2 * th;
            float2 v0 = make_float2(acc[mt][nt][0], acc[mt][nt][1]);
            float2 v1 = make_float2(acc[mt][nt][2], acc[mt][nt][3]);
            if (BIAS) {
                float2 bb = *(const float2*)(bias + c0);
                v0.x += bb.x; v0.y += bb.y;
                v1.x += bb.x; v1.y += bb.y;
            }
            if (RELU) {
                v0.x = fmaxf(v0.x, 0.f); v0.y = fmaxf(v0.y, 0.f);
                v1.x = fmaxf(v1.x, 0.f); v1.y = fmaxf(v1.y, 0.f);
            }
            if (HOUT) {
                *(__half2*)(Ch + (size_t)r0 * N + c0)       = __floats2half2_rn(v0.x, v0.y);
                *(__half2*)(Ch + (size_t)(r0 + 8) * N + c0) = __floats2half2_rn(v1.x, v1.y);
            } else {
                *(float2*)(Cf + (size_t)r0 * N + c0)       = v0;
                *(float2*)(Cf + (size_t)(r0 + 8) * N + c0) = v1;
            }
        }
    }
}

// ---------------------------------------------------------------------------
// Flash attention (exact R9/R13 form): FP16 mma (fp32 acc), P in registers,
// Q pre-scaled by 0.125, __expf softmax, double-buffered K/V tiles.
// grid = (SEQ/128, NHEAD, BATCH), 256 threads (8 warps), 16 q-rows per warp.
// smem: K0,V0,K1,V1 = 4 * 64*72 halves = 36,864 B.
// ---------------------------------------------------------------------------
#define ALD   72
#define ATILE (64 * ALD)
#define AT_SMEM (4 * ATILE * (int)sizeof(__half))

__global__ __launch_bounds__(256)
void flash_attn_h(const __half* __restrict__ qkv, __half* __restrict__ ctx) {
    extern __shared__ __half asm_[];

    const int tid  = threadIdx.x;
    const int lane = tid & 31;
    const int warp = tid >> 5;
    const int g    = lane >> 2;
    const int th   = lane & 3;
    const int lrow = lane & 7;
    const int lgrp = lane >> 3;
    const int qt   = blockIdx.x;
    const int h    = blockIdx.y;
    const int b    = blockIdx.z;

    const size_t base = (size_t)b * SEQ * QLD + (size_t)h * DK;
    const __half* qp = qkv + base;
    const __half* kp = qkv + base + DMODEL;
    const __half* vp = qkv + base + 2 * DMODEL;

    const int qrow = warp * 16 + g;

    uint32_t koff[4], voff[4];
#pragma unroll
    for (int p = 0; p < 4; p++) {
        koff[p] = (uint32_t)(((p * 16 + (lgrp >> 1) * 8 + lrow) * ALD
                              + (lgrp & 1) * 8) * 2);
        voff[p] = (uint32_t)((((lgrp & 1) * 8 + lrow) * ALD
                              + p * 16 + (lgrp >> 1) * 8) * 2);
    }

    auto load_kv = [&](int kt) {
        __half* kd = asm_ + (kt & 1) * 2 * ATILE;
        __half* vd = kd + ATILE;
#pragma unroll
        for (int i = 0; i < 2; i++) {
            int c = tid + i * 256;
            int r = c >> 3, off = (c & 7) * 8;
            size_t go = (size_t)(kt * 64 + r) * QLD + off;
            cp_async16(smem_u32(kd + r * ALD + off), kp + go);
            cp_async16(smem_u32(vd + r * ALD + off), vp + go);
        }
        cp_commit();
    };
    load_kv(0);

    // ---- stage Q (pre-scaled by 0.125, exact) into buffer-1 region ----
    __half* Qs = asm_ + 2 * ATILE;
    const __half2 qsc = __float2half2_rn(0.125f);
    for (int e = tid; e < 128 * 16; e += 256) {
        int r = e >> 4, d4 = (e & 15) * 4;
        uint2 u = *(const uint2*)(qp + (size_t)(qt * 128 + r) * QLD + d4);
        __half2 h0 = __hmul2(*(__half2*)&u.x, qsc);
        __half2 h1 = __hmul2(*(__half2*)&u.y, qsc);
        uint2 w;
        w.x = *(uint32_t*)&h0;
        w.y = *(uint32_t*)&h1;
        *(uint2*)&Qs[r * ALD + d4] = w;
    }
    __syncthreads();

    const uint32_t qoff = (uint32_t)(((warp * 16 + (lgrp & 1) * 8 + lrow) * ALD
                                      + (lgrp >> 1) * 8) * 2);
    uint32_t qf[4][4];
#pragma unroll
    for (int ks = 0; ks < 4; ks++)
        ldsm_x4(qf[ks], smem_u32(Qs) + qoff + ks * 32);

    float m0 = -1e30f, m1 = -1e30f, l0 = 0.f, l1 = 0.f;
    float o[8][4];
#pragma unroll
    for (int i = 0; i < 8; i++)
#pragma unroll
        for (int j = 0; j < 4; j++) o[i][j] = 0.f;

    for (int kt = 0; kt < SEQ / 64; kt++) {
        cp_wait0();
        __syncthreads();
        if (kt + 1 < SEQ / 64) load_kv(kt + 1);

        const uint32_t kbase = smem_u32(asm_ + (kt & 1) * 2 * ATILE);
        const uint32_t vbase = kbase + ATILE * 2;

        // ---- S = (Q/8) @ K^T ----
        float s[8][4];
#pragma unroll
        for (int nt = 0; nt < 8; nt++)
#pragma unroll
            for (int r = 0; r < 4; r++) s[nt][r] = 0.f;

#pragma unroll
        for (int ks = 0; ks < 4; ks++) {
            const uint32_t k0b = ks * 32;
#pragma unroll
            for (int p = 0; p < 4; p++) {
                uint32_t kf[4];
                ldsm_x4(kf, kbase + koff[p] + k0b);
                mma_f16(s[2 * p],     qf[ks], kf[0], kf[1]);
                mma_f16(s[2 * p + 1], qf[ks], kf[2], kf[3]);
            }
        }

        // ---- online softmax; P packed straight into mma A-fragments ----
        float rm0 = -1e30f, rm1 = -1e30f;
#pragma unroll
        for (int nt = 0; nt < 8; nt++) {
            rm0 = fmaxf(rm0, fmaxf(s[nt][0], s[nt][1]));
            rm1 = fmaxf(rm1, fmaxf(s[nt][2], s[nt][3]));
        }
        rm0 = fmaxf(rm0, __shfl_xor_sync(0xffffffffu, rm0, 1));
        rm0 = fmaxf(rm0, __shfl_xor_sync(0xffffffffu, rm0, 2));
        rm1 = fmaxf(rm1, __shfl_xor_sync(0xffffffffu, rm1, 1));
        rm1 = fmaxf(rm1, __shfl_xor_sync(0xffffffffu, rm1, 2));

        const float mn0 = fmaxf(m0, rm0);
        const float mn1 = fmaxf(m1, rm1);
        const float corr0 = __expf(m0 - mn0);
        const float corr1 = __expf(m1 - mn1);

        uint32_t pf[8][2];
        float rs0 = 0.f, rs1 = 0.f;
#pragma unroll
        for (int nt = 0; nt < 8; nt++) {
            float p00 = __expf(s[nt][0] - mn0);
            float p01 = __expf(s[nt][1] - mn0);
            float p10 = __expf(s[nt][2] - mn1);
            float p11 = __expf(s[nt][3] - mn1);
            rs0 += p00 + p01;
            rs1 += p10 + p11;
            __half2 h0 = __floats2half2_rn(p00, p01);
            __half2 h1 = __floats2half2_rn(p10, p11);
            pf[nt][0] = *(uint32_t*)&h0;
            pf[nt][1] = *(uint32_t*)&h1;
        }
        rs0 += __shfl_xor_sync(0xffffffffu, rs0, 1);
        rs0 += __shfl_xor_sync(0xffffffffu, rs0, 2);
        rs1 += __shfl_xor_sync(0xffffffffu, rs1, 1);
        rs1 += __shfl_xor_sync(0xffffffffu, rs1, 2);

        l0 = l0 * corr0 + rs0;
        l1 = l1 * corr1 + rs1;
        m0 = mn0;
        m1 = mn1;

#pragma unroll
        for (int dt = 0; dt < 8; dt++) {
            o[dt][0] *= corr0; o[dt][1] *= corr0;
            o[dt][2] *= corr1; o[dt][3] *= corr1;
        }

        // ---- O += P @ V (A-frags from registers; V via ldmatrix.trans) ----
#pragma unroll
        for (int ks = 0; ks < 4; ks++) {
            uint32_t af[4];
            af[0] = pf[2 * ks][0];
            af[1] = pf[2 * ks][1];
            af[2] = pf[2 * ks + 1][0];
            af[3] = pf[2 * ks + 1][1];
            const uint32_t kvb = (uint32_t)(ks * 16 * ALD * 2);
#pragma unroll
            for (int p = 0; p < 4; p++) {
                uint32_t vf[4];
                ldsm_x4_trans(vf, vbase + voff[p] + kvb);
                mma_f16(o[2 * p],     af, vf[0], vf[1]);
                mma_f16(o[2 * p + 1], af, vf[2], vf[3]);
            }
        }
    }

    // epilogue -> fp16 ctx (stride DMODEL)
    const float inv0 = 1.0f / l0;
    const float inv1 = 1.0f / l1;
    const size_t cbase = (size_t)b * SEQ * DMODEL + (size_t)h * DK;
    const size_t row0 = cbase + (size_t)(qt * 128 + qrow) * DMODEL;
    const size_t row1 = cbase + (size_t)(qt * 128 + qrow + 8) * DMODEL;
#pragma unroll
    for (int dt = 0; dt < 8; dt++) {
        const int c0 = dt * 8 + 2 * th;
        *(__half2*)(ctx + row0 + c0) = __floats2half2_rn(o[dt][0] * inv0, o[dt][1] * inv0);
        *(__half2*)(ctx + row1 + c0) = __floats2half2_rn(o[dt][2] * inv1, o[dt][3] * inv1);
    }
}

// ---------------------------------------------------------------------------
// out = LayerNorm(a + b) * gamma + beta; b fp16. Optional fp16 result copy.
// ---------------------------------------------------------------------------
__global__ __launch_bounds__(256)
void add_ln_kernel(const float* __restrict__ a, const __half* __restrict__ b,
                   const float* __restrict__ gamma, const float* __restrict__ beta,
                   float* __restrict__ out, __half* __restrict__ out_h) {
    const int row = blockIdx.x;
    const int tid = threadIdx.x;
    const size_t off = (size_t)row * DMODEL;

    __shared__ float r1[8], r2[8];

    float vals[4];
    float sum = 0.f, sq = 0.f;
#pragma unroll
    for (int t = 0; t < 4; t++) {
        int c = tid + t * 256;
        float vv = a[off + c] + __half2float(b[off + c]);
        vals[t] = vv;
        sum += vv;
        sq  += vv * vv;
    }
#pragma unroll
    for (int o = 16; o > 0; o >>= 1) {
        sum += __shfl_xor_sync(0xffffffffu, sum, o);
        sq  += __shfl_xor_sync(0xffffffffu, sq,  o);
    }
    const int wid = tid >> 5;
    if ((tid & 31) == 0) { r1[wid] = sum; r2[wid] = sq; }
    __syncthreads();
    float tot1 = 0.f, tot2 = 0.f;
#pragma unroll
    for (int w = 0; w < 8; w++) { tot1 += r1[w]; tot2 += r2[w]; }

    const float mu   = tot1 * (1.0f / DMODEL);
    const float var  = tot2 * (1.0f / DMODEL) - mu * mu;
    const float rstd = rsqrtf(var + LN_EPS);

#pragma unroll
    for (int t = 0; t < 4; t++) {
        int c = tid + t * 256;
        float y = (vals[t] - mu) * rstd * gamma[c] + beta[c];
        out[off + c] = y;
        if (out_h) out_h[off + c] = __float2half(y);
    }
}

// ---------------------------------------------------------------------------
// Launcher
// ---------------------------------------------------------------------------
extern "C" void kernel_launch(void* const* d_in, const int* in_sizes, int n_in,
                              void* d_out, int out_size) {
    (void)in_sizes; (void)n_in; (void)out_size;
    const float* x   = (const float*)d_in[0];
    const float* wq  = (const float*)d_in[1];
    const float* wk  = (const float*)d_in[2];
    const float* wv  = (const float*)d_in[3];
    const float* wo  = (const float*)d_in[4];
    const float* w1  = (const float*)d_in[5];
    const float* b1  = (const float*)d_in[6];
    const float* w2  = (const float*)d_in[7];
    const float* b2  = (const float*)d_in[8];
    const float* g1  = (const float*)d_in[9];
    const float* be1 = (const float*)d_in[10];
    const float* g2  = (const float*)d_in[11];
    const float* be2 = (const float*)d_in[12];
    float* out = (float*)d_out;

    __half *xh, *qkvh, *ctxh, *hrh, *ffh, *attnh, *f2h;
    __half *wqkvh, *woh, *w1h, *w2h;
    float *h;
    cudaGetSymbolAddress((void**)&xh,    g_xh);
    cudaGetSymbolAddress((void**)&qkvh,  g_qkvh);
    cudaGetSymbolAddress((void**)&ctxh,  g_ctxh);
    cudaGetSymbolAddress((void**)&hrh,   g_hrh);
    cudaGetSymbolAddress((void**)&ffh,   g_ffh);
    cudaGetSymbolAddress((void**)&attnh, g_attnh);
    cudaGetSymbolAddress((void**)&f2h,   g_f2h);
    cudaGetSymbolAddress((void**)&h,     g_h);
    cudaGetSymbolAddress((void**)&wqkvh, g_wqkvh);
    cudaGetSymbolAddress((void**)&woh,   g_woh);
    cudaGetSymbolAddress((void**)&w1h,   g_w1h);
    cudaGetSymbolAddress((void**)&w2h,   g_w2h);

    cudaFuncSetAttribute(hgemm<false, false, true>,
                         cudaFuncAttributeMaxDynamicSharedMemorySize, HGEMM_SMEM);
    cudaFuncSetAttribute(hgemm<true, true, true>,
                         cudaFuncAttributeMaxDynamicSharedMemorySize, HGEMM_SMEM);
    cudaFuncSetAttribute(hgemm<true, false, true>,
                         cudaFuncAttributeMaxDynamicSharedMemorySize, HGEMM_SMEM);
    cudaFuncSetAttribute(flash_attn_h,
                         cudaFuncAttributeMaxDynamicSharedMemorySize, AT_SMEM);

    // ---- fused prep: one launch converts everything to fp16 ----
    prep_all_kernel<<<(U_TOT + 255) / 256, 256>>>(x, wq, wk, wv, wo, w1, w2,
                                                  xh, wqkvh, woh, w1h, w2h);

    const dim3 g_qkv(QLD / 128,    NTOK / 64);    // (24, 128)
    const dim3 g_dd (DMODEL / 128, NTOK / 64);    // (8, 128)
    const dim3 g_df (DFF / 128,    NTOK / 64);    // (32, 128)

    // fused QKV projection -> packed fp16 [tok][3072]
    hgemm<false, false, true><<<g_qkv, 256, HGEMM_SMEM>>>(xh, wqkvh, nullptr, qkvh,
                                                          NTOK, QLD, DMODEL);

    // attention -> fp16 ctx
    flash_attn_h<<<dim3(SEQ / 128, NHEAD, BATCH), 256, AT_SMEM>>>(qkvh, ctxh);

    // output projection -> fp16 (feeds add_ln only)
    hgemm<false, false, true><<<g_dd, 256, HGEMM_SMEM>>>(ctxh, woh, nullptr, attnh,
                                                         NTOK, DMODEL, DMODEL);

    // add & norm 1 (h fp32 residual, hrh fp16 for FFN1)
    add_ln_kernel<<<NTOK, 256>>>(x, attnh, g1, be1, h, hrh);

    // FFN
    hgemm<true, true,  true><<<g_df, 256, HGEMM_SMEM>>>(hrh, w1h, b1, ffh, NTOK, DFF,    DMODEL);
    hgemm<true, false, true><<<g_dd, 256, HGEMM_SMEM>>>(ffh, w2h, b2, f2h, NTOK, DMODEL, DFF);

    // add & norm 2
    add_ln_kernel<<<NTOK, 256>>>(h, f2h, g2, be2, out, nullptr);
}

// round 15
// speedup vs baseline: 1.0704x; 1.0704x over previous
#include <cuda_runtime.h>
#include <cuda_fp16.h>
#include <math.h>
#include <stdint.h>

// ---------------------------------------------------------------------------
// Problem constants
// ---------------------------------------------------------------------------
#define BATCH   4
#define SEQ     2048
#define DMODEL  1024
#define NHEAD   16
#define DK      64
#define DFF     4096
#define NTOK    (BATCH * SEQ)          // 8192
#define LN_EPS  1e-5f
#define QLD     (3 * DMODEL)           // packed qkv row stride

// ---------------------------------------------------------------------------
// Scratch (device globals — allocation-free rule)
// ---------------------------------------------------------------------------
__device__ __half g_xh   [NTOK * DMODEL];
__device__ __half g_qkvh [NTOK * QLD];
__device__ __half g_ctxh [NTOK * DMODEL];
__device__ __half g_hrh  [NTOK * DMODEL];
__device__ __half g_ffh  [NTOK * DFF];
__device__ float  g_attn [NTOK * DMODEL];
__device__ float  g_h    [NTOK * DMODEL];
__device__ float  g_f2   [NTOK * DMODEL];
// fp16 ROW-MAJOR weights: wh[k][n] = (half)w[k][n]
__device__ __half g_wqkvh[DMODEL * QLD];
__device__ __half g_woh  [DMODEL * DMODEL];
__device__ __half g_w1h  [DMODEL * DFF];
__device__ __half g_w2h  [DFF * DMODEL];

// ---------------------------------------------------------------------------
// Helpers
// ---------------------------------------------------------------------------
__device__ __forceinline__ uint32_t smem_u32(const void* p) {
    return (uint32_t)__cvta_generic_to_shared(p);
}
__device__ __forceinline__ void cp_async16(uint32_t dst, const void* src) {
    asm volatile("cp.async.cg.shared.global [%0], [%1], 16;\n" :: "r"(dst), "l"(src));
}
__device__ __forceinline__ void cp_commit() { asm volatile("cp.async.commit_group;\n"); }
__device__ __forceinline__ void cp_wait1()  { asm volatile("cp.async.wait_group 1;\n"); }
__device__ __forceinline__ void cp_wait0()  { asm volatile("cp.async.wait_group 0;\n"); }

// mma.m16n8k16 row.col f32 += f16 * f16
__device__ __forceinline__ void mma_f16(float* c, const uint32_t* a,
                                        uint32_t b0, uint32_t b1) {
    asm volatile(
        "mma.sync.aligned.m16n8k16.row.col.f32.f16.f16.f32 "
        "{%0,%1,%2,%3}, {%4,%5,%6,%7}, {%8,%9}, {%0,%1,%2,%3};"
        : "+f"(c[0]), "+f"(c[1]), "+f"(c[2]), "+f"(c[3])
        : "r"(a[0]), "r"(a[1]), "r"(a[2]), "r"(a[3]), "r"(b0), "r"(b1));
}

__device__ __forceinline__ void ldsm_x4(uint32_t* r, uint32_t addr) {
    asm volatile("ldmatrix.sync.aligned.m8n8.x4.shared.b16 {%0,%1,%2,%3}, [%4];"
                 : "=r"(r[0]), "=r"(r[1]), "=r"(r[2]), "=r"(r[3]) : "r"(addr));
}
__device__ __forceinline__ void ldsm_x4_trans(uint32_t* r, uint32_t addr) {
    asm volatile("ldmatrix.sync.aligned.m8n8.x4.trans.shared.b16 {%0,%1,%2,%3}, [%4];"
                 : "=r"(r[0]), "=r"(r[1]), "=r"(r[2]), "=r"(r[3]) : "r"(addr));
}

// ---------------------------------------------------------------------------
// Fused prep: one launch converts x + all weights to fp16 (qkv packed).
// ---------------------------------------------------------------------------
#define U_X   (NTOK * DMODEL / 4)
#define U_W   (DMODEL * DMODEL / 4)
#define U_F   (DMODEL * DFF / 4)
#define U_TOT (U_X + 4 * U_W + 2 * U_F)

__device__ __forceinline__ void cv_lin(const float* in, __half* out, int i) {
    float4 v = *(const float4*)(in + 4 * (size_t)i);
    *(__half2*)(out + 4 * (size_t)i)     = __floats2half2_rn(v.x, v.y);
    *(__half2*)(out + 4 * (size_t)i + 2) = __floats2half2_rn(v.z, v.w);
}
__device__ __forceinline__ void cv_pack(const float* in, __half* out, int i, int off) {
    int row = i >> 8, c4 = (i & 255) * 4;
    float4 v = *(const float4*)(in + (size_t)row * DMODEL + c4);
    __half* o = out + (size_t)row * QLD + off + c4;
    *(__half2*)o       = __floats2half2_rn(v.x, v.y);
    *(__half2*)(o + 2) = __floats2half2_rn(v.z, v.w);
}

__global__ __launch_bounds__(256)
void prep_all_kernel(const float* __restrict__ x,
                     const float* __restrict__ wq, const float* __restrict__ wk,
                     const float* __restrict__ wv, const float* __restrict__ wo,
                     const float* __restrict__ w1, const float* __restrict__ w2,
                     __half* __restrict__ xh, __half* __restrict__ wqkvh,
                     __half* __restrict__ woh, __half* __restrict__ w1h,
                     __half* __restrict__ w2h) {
    int i = blockIdx.x * blockDim.x + threadIdx.x;
    if (i >= U_TOT) return;
    if (i < U_X)            { cv_lin(x, xh, i); return; }
    i -= U_X;
    if (i < U_W)            { cv_pack(wq, wqkvh, i, 0);          return; }
    i -= U_W;
    if (i < U_W)            { cv_pack(wk, wqkvh, i, DMODEL);     return; }
    i -= U_W;
    if (i < U_W)            { cv_pack(wv, wqkvh, i, 2 * DMODEL); return; }
    i -= U_W;
    if (i < U_W)            { cv_lin(wo, woh, i); return; }
    i -= U_W;
    if (i < U_F)            { cv_lin(w1, w1h, i); return; }
    i -= U_F;
    cv_lin(w2, w2h, i);
}

// ---------------------------------------------------------------------------
// FP16 GEMM, ldmatrix fragments, 3-stage cp.async, ONE sync per k-iter.
// C[M,N] = A[M,K] @ B[K,N] (+bias)(+relu). A row-major, B row-major
// (fragments via ldmatrix.trans). 128x128 tile, BK=64, 8 warps.
// ---------------------------------------------------------------------------
#define HLD  72
#define BLD  136
#define HA_H (128 * HLD)
#define HB_H (64 * BLD)
#define HSTAGE_ALL (HA_H + HB_H)
#define HGEMM_SMEM (3 * HSTAGE_ALL * (int)sizeof(__half))

template<bool BIAS, bool RELU, bool HOUT>
__global__ __launch_bounds__(256, 2)
void hgemm(const __half* __restrict__ A, const __half* __restrict__ B,
           const float* __restrict__ bias, void* __restrict__ Cv,
           int M, int N, int K) {
    extern __shared__ __half hsm[];

    const int tid  = threadIdx.x;
    const int lane = tid & 31;
    const int warp = tid >> 5;
    const int wm   = warp & 1;
    const int wn   = warp >> 1;
    const int g    = lane >> 2;
    const int th   = lane & 3;
    const int lrow = lane & 7;
    const int lgrp = lane >> 3;

    const int rowBase = blockIdx.y * 128;
    const int colBase = blockIdx.x * 128;

    float acc[4][4][4];
#pragma unroll
    for (int i = 0; i < 4; i++)
#pragma unroll
        for (int j = 0; j < 4; j++)
#pragma unroll
            for (int r = 0; r < 4; r++) acc[i][j][r] = 0.f;

    uint32_t aoff[4], boff[2];
#pragma unroll
    for (int mt = 0; mt < 4; mt++)
        aoff[mt] = (uint32_t)(((wm * 64 + mt * 16 + (lgrp & 1) * 8 + lrow) * HLD
                               + (lgrp >> 1) * 8) * 2);
#pragma unroll
    for (int p = 0; p < 2; p++)
        boff[p] = (uint32_t)((((lgrp & 1) * 8 + lrow) * BLD
                              + wn * 32 + p * 16 + (lgrp >> 1) * 8) * 2
                             + HA_H * 2);

    auto load_chunk = [&](int c) {
        const int s = c % 3;
        __half* as = hsm + s * HSTAGE_ALL;
        __half* bs = as + HA_H;
        const size_t koff = (size_t)c * 64;
#pragma unroll
        for (int p = 0; p < 4; p++) {
            int idx = tid + p * 256;
            int ra = idx >> 3, ja = (idx & 7) * 8;
            cp_async16(smem_u32(as + ra * HLD + ja),
                       A + (size_t)(rowBase + ra) * K + koff + ja);
            int rb = idx >> 4, jb = (idx & 15) * 8;
            cp_async16(smem_u32(bs + rb * BLD + jb),
                       B + (koff + rb) * N + colBase + jb);
        }
        cp_commit();
    };

    const int nk = K / 64;
    load_chunk(0);
    load_chunk(1);

    for (int it = 0; it < nk; it++) {
        const int s = it % 3;
        if (it + 1 < nk) cp_wait1();     // stage `it` ready; it+1 may fly
        else             cp_wait0();
        __syncthreads();                 // all warps done with stage it-1
        if (it + 2 < nk) load_chunk(it + 2);   // overwrites stage it-1: safe

        const uint32_t sbase = smem_u32(hsm + s * HSTAGE_ALL);
#pragma unroll
        for (int ks = 0; ks < 4; ks++) {
            uint32_t af[4][4], bf[2][4];
#pragma unroll
            for (int mt = 0; mt < 4; mt++)
                ldsm_x4(af[mt], sbase + aoff[mt] + ks * 32);
#pragma unroll
            for (int p = 0; p < 2; p++)
                ldsm_x4_trans(bf[p], sbase + boff[p] + (uint32_t)(ks * 16 * BLD * 2));
#pragma unroll
            for (int mt = 0; mt < 4; mt++) {
                mma_f16(acc[mt][0], af[mt], bf[0][0], bf[0][1]);
                mma_f16(acc[mt][1], af[mt], bf[0][2], bf[0][3]);
                mma_f16(acc[mt][2], af[mt], bf[1][0], bf[1][1]);
                mma_f16(acc[mt][3], af[mt], bf[1][2], bf[1][3]);
            }
        }
    }

    float* Cf = (float*)Cv;
    __half* Ch = (__half*)Cv;
#pragma unroll
    for (int mt = 0; mt < 4; mt++) {
        const int r0 = rowBase + wm * 64 + mt * 16 + g;
#pragma unroll
        for (int nt = 0; nt < 4; nt++) {
            const int c0 = colBase + wn * 32 + nt * 8 + 2 * th;
            float2 v0 = make_float2(acc[mt][nt][0], acc[mt][nt][1]);
            float2 v1 = make_float2(acc[mt][nt][2], acc[mt][nt][3]);
            if (BIAS) {
                float2 bb = *(const float2*)(bias + c0);
                v0.x += bb.x; v0.y += bb.y;
                v1.x += bb.x; v1.y += bb.y;
            }
            if (RELU) {
                v0.x = fmaxf(v0.x, 0.f); v0.y = fmaxf(v0.y, 0.f);
                v1.x = fmaxf(v1.x, 0.f); v1.y = fmaxf(v1.y, 0.f);
            }
            if (HOUT) {
                *(__half2*)(Ch + (size_t)r0 * N + c0)       = __floats2half2_rn(v0.x, v0.y);
                *(__half2*)(Ch + (size_t)(r0 + 8) * N + c0) = __floats2half2_rn(v1.x, v1.y);
            } else {
                *(float2*)(Cf + (size_t)r0 * N + c0)       = v0;
                *(float2*)(Cf + (size_t)(r0 + 8) * N + c0) = v1;
            }
        }
    }
}

// ---------------------------------------------------------------------------
// Flash attention: FP16 mma, P kept in registers (no smem round-trip),
// Q pre-scaled by 1/8 (exact), double-buffered K/V, ONE sync per kv tile.
// Reads packed qkv [tok][3072]: q at +0, k at +1024, v at +2048.
// grid = (SEQ/128, NHEAD, BATCH), 256 threads (8 warps), 16 q-rows per warp.
// smem: K0,V0,K1,V1 = 4 * 64*72 halves = 36,864 B (Q staged in K1/V1 region).
// ---------------------------------------------------------------------------
#define ALD   72
#define ATILE (64 * ALD)
#define AT_SMEM (4 * ATILE * (int)sizeof(__half))

__global__ __launch_bounds__(256)
void flash_attn_h(const __half* __restrict__ qkv, __half* __restrict__ ctx) {
    extern __shared__ __half asm_[];

    const int tid  = threadIdx.x;
    const int lane = tid & 31;
    const int warp = tid >> 5;         // 0..7 -> 16 q rows each
    const int g    = lane >> 2;
    const int th   = lane & 3;
    const int lrow = lane & 7;
    const int lgrp = lane >> 3;
    const int qt   = blockIdx.x;
    const int h    = blockIdx.y;
    const int b    = blockIdx.z;

    const size_t base = (size_t)b * SEQ * QLD + (size_t)h * DK;
    const __half* qp = qkv + base;
    const __half* kp = qkv + base + DMODEL;
    const __half* vp = qkv + base + 2 * DMODEL;

    const int qrow = warp * 16 + g;    // row pair: qrow, qrow+8

    uint32_t koff[4], voff[4];
#pragma unroll
    for (int p = 0; p < 4; p++) {
        koff[p] = (uint32_t)(((p * 16 + (lgrp >> 1) * 8 + lrow) * ALD
                              + (lgrp & 1) * 8) * 2);
        voff[p] = (uint32_t)((((lgrp & 1) * 8 + lrow) * ALD
                              + p * 16 + (lgrp >> 1) * 8) * 2);
    }

    auto load_kv = [&](int kt) {
        __half* kd = asm_ + (kt & 1) * 2 * ATILE;
        __half* vd = kd + ATILE;
#pragma unroll
        for (int i = 0; i < 2; i++) {
            int c = tid + i * 256;              // 0..511
            int r = c >> 3, off = (c & 7) * 8;
            size_t go = (size_t)(kt * 64 + r) * QLD + off;
            cp_async16(smem_u32(kd + r * ALD + off), kp + go);
            cp_async16(smem_u32(vd + r * ALD + off), vp + go);
        }
        cp_commit();
    };
    load_kv(0);                         // -> buffer 0

    // ---- stage Q (pre-scaled by 0.125, exact) into buffer-1 region ----
    __half* Qs = asm_ + 2 * ATILE;      // 128 rows x 72 fits in K1+V1
    const __half2 qsc = __float2half2_rn(0.125f);
    for (int e = tid; e < 128 * 16; e += 256) {
        int r = e >> 4, d4 = (e & 15) * 4;
        uint2 u = *(const uint2*)(qp + (size_t)(qt * 128 + r) * QLD + d4);
        __half2 h0 = __hmul2(*(__half2*)&u.x, qsc);
        __half2 h1 = __hmul2(*(__half2*)&u.y, qsc);
        uint2 w;
        w.x = *(uint32_t*)&h0;
        w.y = *(uint32_t*)&h1;
        *(uint2*)&Qs[r * ALD + d4] = w;
    }
    __syncthreads();

    const uint32_t qoff = (uint32_t)(((warp * 16 + (lgrp & 1) * 8 + lrow) * ALD
                                      + (lgrp >> 1) * 8) * 2);
    uint32_t qf[4][4];
#pragma unroll
    for (int ks = 0; ks < 4; ks++)
        ldsm_x4(qf[ks], smem_u32(Qs) + qoff + ks * 32);

    float m0 = -1e30f, m1 = -1e30f, l0 = 0.f, l1 = 0.f;
    float o[8][4];
#pragma unroll
    for (int i = 0; i < 8; i++)
#pragma unroll
        for (int j = 0; j < 4; j++) o[i][j] = 0.f;

    for (int kt = 0; kt < SEQ / 64; kt++) {
        cp_wait0();                     // KV tile kt landed
        __syncthreads();                // everyone done with buffer kt-1 (and Q ldsm at kt=0)
        if (kt + 1 < SEQ / 64) load_kv(kt + 1);   // overwrites buffer kt-1: safe

        const uint32_t kbase = smem_u32(asm_ + (kt & 1) * 2 * ATILE);
        const uint32_t vbase = kbase + ATILE * 2;   // bytes

        // ---- S = (Q/8) @ K^T ----
        float s[8][4];
#pragma unroll
        for (int nt = 0; nt < 8; nt++)
#pragma unroll
            for (int r = 0; r < 4; r++) s[nt][r] = 0.f;

#pragma unroll
        for (int ks = 0; ks < 4; ks++) {
            const uint32_t k0b = ks * 32;
#pragma unroll
            for (int p = 0; p < 4; p++) {
                uint32_t kf[4];
                ldsm_x4(kf, kbase + koff[p] + k0b);
                mma_f16(s[2 * p],     qf[ks], kf[0], kf[1]);
                mma_f16(s[2 * p + 1], qf[ks], kf[2], kf[3]);
            }
        }

        // ---- online softmax; P packed straight into mma A-fragments ----
        float rm0 = -1e30f, rm1 = -1e30f;
#pragma unroll
        for (int nt = 0; nt < 8; nt++) {
            rm0 = fmaxf(rm0, fmaxf(s[nt][0], s[nt][1]));
            rm1 = fmaxf(rm1, fmaxf(s[nt][2], s[nt][3]));
        }
        rm0 = fmaxf(rm0, __shfl_xor_sync(0xffffffffu, rm0, 1));
        rm0 = fmaxf(rm0, __shfl_xor_sync(0xffffffffu, rm0, 2));
        rm1 = fmaxf(rm1, __shfl_xor_sync(0xffffffffu, rm1, 1));
        rm1 = fmaxf(rm1, __shfl_xor_sync(0xffffffffu, rm1, 2));

        const float mn0 = fmaxf(m0, rm0);
        const float mn1 = fmaxf(m1, rm1);
        const float corr0 = __expf(m0 - mn0);
        const float corr1 = __expf(m1 - mn1);

        uint32_t pf[8][2];              // [nt][0]: rows qrow; [1]: rows qrow+8
        float rs0 = 0.f, rs1 = 0.f;
#pragma unroll
        for (int nt = 0; nt < 8; nt++) {
            float p00 = __expf(s[nt][0] - mn0);
            float p01 = __expf(s[nt][1] - mn0);
            float p10 = __expf(s[nt][2] - mn1);
            float p11 = __expf(s[nt][3] - mn1);
            rs0 += p00 + p01;
            rs1 += p10 + p11;
            __half2 h0 = __floats2half2_rn(p00, p01);
            __half2 h1 = __floats2half2_rn(p10, p11);
            pf[nt][0] = *(uint32_t*)&h0;
            pf[nt][1] = *(uint32_t*)&h1;
        }
        rs0 += __shfl_xor_sync(0xffffffffu, rs0, 1);
        rs0 += __shfl_xor_sync(0xffffffffu, rs0, 2);
        rs1 += __shfl_xor_sync(0xffffffffu, rs1, 1);
        rs1 += __shfl_xor_sync(0xffffffffu, rs1, 2);

        l0 = l0 * corr0 + rs0;
        l1 = l1 * corr1 + rs1;
        m0 = mn0;
        m1 = mn1;

#pragma unroll
        for (int dt = 0; dt < 8; dt++) {
            o[dt][0] *= corr0; o[dt][1] *= corr0;
            o[dt][2] *= corr1; o[dt][3] *= corr1;
        }

        // ---- O += P @ V (A-frags from registers; V via ldmatrix.trans) ----
#pragma unroll
        for (int ks = 0; ks < 4; ks++) {
            uint32_t af[4];
            af[0] = pf[2 * ks][0];
            af[1] = pf[2 * ks][1];
            af[2] = pf[2 * ks + 1][0];
            af[3] = pf[2 * ks + 1][1];
            const uint32_t kvb = (uint32_t)(ks * 16 * ALD * 2);
#pragma unroll
            for (int p = 0; p < 4; p++) {
                uint32_t vf[4];
                ldsm_x4_trans(vf, vbase + voff[p] + kvb);
                mma_f16(o[2 * p],     af, vf[0], vf[1]);
                mma_f16(o[2 * p + 1], af, vf[2], vf[3]);
            }
        }
    }

    // epilogue -> fp16 ctx (stride DMODEL)
    const float inv0 = 1.0f / l0;
    const float inv1 = 1.0f / l1;
    const size_t cbase = (size_t)b * SEQ * DMODEL + (size_t)h * DK;
    const size_t row0 = cbase + (size_t)(qt * 128 + qrow) * DMODEL;
    const size_t row1 = cbase + (size_t)(qt * 128 + qrow + 8) * DMODEL;
#pragma unroll
    for (int dt = 0; dt < 8; dt++) {
        const int c0 = dt * 8 + 2 * th;
        *(__half2*)(ctx + row0 + c0) = __floats2half2_rn(o[dt][0] * inv0, o[dt][1] * inv0);
        *(__half2*)(ctx + row1 + c0) = __floats2half2_rn(o[dt][2] * inv1, o[dt][3] * inv1);
    }
}

// ---------------------------------------------------------------------------
// out = LayerNorm(a + b) * gamma + beta; optional fp16 copy for next GEMM.
// ---------------------------------------------------------------------------
__global__ __launch_bounds__(256)
void add_ln_kernel(const float* __restrict__ a, const float* __restrict__ b,
                   const float* __restrict__ gamma, const float* __restrict__ beta,
                   float* __restrict__ out, __half* __restrict__ out_h) {
    const int row = blockIdx.x;
    const int tid = threadIdx.x;
    const size_t off = (size_t)row * DMODEL;

    __shared__ float r1[8], r2[8];

    float vals[4];
    float sum = 0.f, sq = 0.f;
#pragma unroll
    for (int t = 0; t < 4; t++) {
        int c = tid + t * 256;
        float vv = a[off + c] + b[off + c];
        vals[t] = vv;
        sum += vv;
        sq  += vv * vv;
    }
#pragma unroll
    for (int o = 16; o > 0; o >>= 1) {
        sum += __shfl_xor_sync(0xffffffffu, sum, o);
        sq  += __shfl_xor_sync(0xffffffffu, sq,  o);
    }
    const int wid = tid >> 5;
    if ((tid & 31) == 0) { r1[wid] = sum; r2[wid] = sq; }
    __syncthreads();
    float tot1 = 0.f, tot2 = 0.f;
#pragma unroll
    for (int w = 0; w < 8; w++) { tot1 += r1[w]; tot2 += r2[w]; }

    const float mu   = tot1 * (1.0f / DMODEL);
    const float var  = tot2 * (1.0f / DMODEL) - mu * mu;
    const float rstd = rsqrtf(var + LN_EPS);

#pragma unroll
    for (int t = 0; t < 4; t++) {
        int c = tid + t * 256;
        float y = (vals[t] - mu) * rstd * gamma[c] + beta[c];
        out[off + c] = y;
        if (out_h) out_h[off + c] = __float2half(y);
    }
}

// ---------------------------------------------------------------------------
// Launcher
// ---------------------------------------------------------------------------
extern "C" void kernel_launch(void* const* d_in, const int* in_sizes, int n_in,
                              void* d_out, int out_size) {
    (void)in_sizes; (void)n_in; (void)out_size;
    const float* x   = (const float*)d_in[0];
    const float* wq  = (const float*)d_in[1];
    const float* wk  = (const float*)d_in[2];
    const float* wv  = (const float*)d_in[3];
    const float* wo  = (const float*)d_in[4];
    const float* w1  = (const float*)d_in[5];
    const float* b1  = (const float*)d_in[6];
    const float* w2  = (const float*)d_in[7];
    const float* b2  = (const float*)d_in[8];
    const float* g1  = (const float*)d_in[9];
    const float* be1 = (const float*)d_in[10];
    const float* g2  = (const float*)d_in[11];
    const float* be2 = (const float*)d_in[12];
    float* out = (float*)d_out;

    __half *xh, *qkvh, *ctxh, *hrh, *ffh, *wqkvh, *woh, *w1h, *w2h;
    float *attn, *h, *f2;
    cudaGetSymbolAddress((void**)&xh,    g_xh);
    cudaGetSymbolAddress((void**)&qkvh,  g_qkvh);
    cudaGetSymbolAddress((void**)&ctxh,  g_ctxh);
    cudaGetSymbolAddress((void**)&hrh,   g_hrh);
    cudaGetSymbolAddress((void**)&ffh,   g_ffh);
    cudaGetSymbolAddress((void**)&attn,  g_attn);
    cudaGetSymbolAddress((void**)&h,     g_h);
    cudaGetSymbolAddress((void**)&f2,    g_f2);
    cudaGetSymbolAddress((void**)&wqkvh, g_wqkvh);
    cudaGetSymbolAddress((void**)&woh,   g_woh);
    cudaGetSymbolAddress((void**)&w1h,   g_w1h);
    cudaGetSymbolAddress((void**)&w2h,   g_w2h);

    cudaFuncSetAttribute(hgemm<false, false, true>,
                         cudaFuncAttributeMaxDynamicSharedMemorySize, HGEMM_SMEM);
    cudaFuncSetAttribute(hgemm<false, false, false>,
                         cudaFuncAttributeMaxDynamicSharedMemorySize, HGEMM_SMEM);
    cudaFuncSetAttribute(hgemm<true, true, true>,
                         cudaFuncAttributeMaxDynamicSharedMemorySize, HGEMM_SMEM);
    cudaFuncSetAttribute(hgemm<true, false, false>,
                         cudaFuncAttributeMaxDynamicSharedMemorySize, HGEMM_SMEM);
    cudaFuncSetAttribute(flash_attn_h,
                         cudaFuncAttributeMaxDynamicSharedMemorySize, AT_SMEM);

    // ---- fused prep: one launch converts everything to fp16 ----
    prep_all_kernel<<<(U_TOT + 255) / 256, 256>>>(x, wq, wk, wv, wo, w1, w2,
                                                  xh, wqkvh, woh, w1h, w2h);

    const dim3 g_qkv(QLD / 128,    NTOK / 128);   // (24, 64)
    const dim3 g_dd (DMODEL / 128, NTOK / 128);   // (8, 64)
    const dim3 g_df (DFF / 128,    NTOK / 128);   // (32, 64)

    // fused QKV projection -> packed fp16 [tok][3072]
    hgemm<false, false, true><<<g_qkv, 256, HGEMM_SMEM>>>(xh, wqkvh, nullptr, qkvh,
                                                          NTOK, QLD, DMODEL);

    // attention -> fp16 ctx
    flash_attn_h<<<dim3(SEQ / 128, NHEAD, BATCH), 256, AT_SMEM>>>(qkvh, ctxh);

    // output projection -> fp32
    hgemm<false, false, false><<<g_dd, 256, HGEMM_SMEM>>>(ctxh, woh, nullptr, attn,
                                                          NTOK, DMODEL, DMODEL);

    // add & norm 1 (h fp32 residual, hrh fp16 for FFN1)
    add_ln_kernel<<<NTOK, 256>>>(x, attn, g1, be1, h, hrh);

    // FFN
    hgemm<true, true,  true ><<<g_df, 256, HGEMM_SMEM>>>(hrh, w1h, b1, ffh, NTOK, DFF,    DMODEL);
    hgemm<true, false, false><<<g_dd, 256, HGEMM_SMEM>>>(ffh, w2h, b2, f2,  NTOK, DMODEL, DFF);

    // add & norm 2
    add_ln_kernel<<<NTOK, 256>>>(h, f2, g2, be2, out, nullptr);
}

// round 16
// speedup vs baseline: 1.0709x; 1.0005x over previous
#include <cuda_runtime.h>
#include <cuda_fp16.h>
#include <math.h>
#include <stdint.h>

// ---------------------------------------------------------------------------
// Problem constants
// ---------------------------------------------------------------------------
#define BATCH   4
#define SEQ     2048
#define DMODEL  1024
#define NHEAD   16
#define DK      64
#define DFF     4096
#define NTOK    (BATCH * SEQ)          // 8192
#define LN_EPS  1e-5f
#define QLD     (3 * DMODEL)           // packed qkv row stride

// ---------------------------------------------------------------------------
// Scratch (device globals — allocation-free rule)
// ---------------------------------------------------------------------------
__device__ __half g_xh   [NTOK * DMODEL];
__device__ __half g_qkvh [NTOK * QLD];
__device__ __half g_ctxh [NTOK * DMODEL];
__device__ __half g_hrh  [NTOK * DMODEL];
__device__ __half g_ffh  [NTOK * DFF];
__device__ float  g_attn [NTOK * DMODEL];
__device__ float  g_h    [NTOK * DMODEL];
__device__ float  g_f2   [NTOK * DMODEL];
// fp16 ROW-MAJOR weights: wh[k][n] = (half)w[k][n]
__device__ __half g_wqkvh[DMODEL * QLD];
__device__ __half g_woh  [DMODEL * DMODEL];
__device__ __half g_w1h  [DMODEL * DFF];
__device__ __half g_w2h  [DFF * DMODEL];

// ---------------------------------------------------------------------------
// Helpers
// ---------------------------------------------------------------------------
__device__ __forceinline__ uint32_t smem_u32(const void* p) {
    return (uint32_t)__cvta_generic_to_shared(p);
}
__device__ __forceinline__ void cp_async16(uint32_t dst, const void* src) {
    asm volatile("cp.async.cg.shared.global [%0], [%1], 16;\n" :: "r"(dst), "l"(src));
}
__device__ __forceinline__ void cp_commit() { asm volatile("cp.async.commit_group;\n"); }
__device__ __forceinline__ void cp_wait1()  { asm volatile("cp.async.wait_group 1;\n"); }
__device__ __forceinline__ void cp_wait0()  { asm volatile("cp.async.wait_group 0;\n"); }

// mma.m16n8k16 row.col f32 += f16 * f16
__device__ __forceinline__ void mma_f16(float* c, const uint32_t* a,
                                        uint32_t b0, uint32_t b1) {
    asm volatile(
        "mma.sync.aligned.m16n8k16.row.col.f32.f16.f16.f32 "
        "{%0,%1,%2,%3}, {%4,%5,%6,%7}, {%8,%9}, {%0,%1,%2,%3};"
        : "+f"(c[0]), "+f"(c[1]), "+f"(c[2]), "+f"(c[3])
        : "r"(a[0]), "r"(a[1]), "r"(a[2]), "r"(a[3]), "r"(b0), "r"(b1));
}

__device__ __forceinline__ void ldsm_x4(uint32_t* r, uint32_t addr) {
    asm volatile("ldmatrix.sync.aligned.m8n8.x4.shared.b16 {%0,%1,%2,%3}, [%4];"
                 : "=r"(r[0]), "=r"(r[1]), "=r"(r[2]), "=r"(r[3]) : "r"(addr));
}
__device__ __forceinline__ void ldsm_x4_trans(uint32_t* r, uint32_t addr) {
    asm volatile("ldmatrix.sync.aligned.m8n8.x4.trans.shared.b16 {%0,%1,%2,%3}, [%4];"
                 : "=r"(r[0]), "=r"(r[1]), "=r"(r[2]), "=r"(r[3]) : "r"(addr));
}

// ---------------------------------------------------------------------------
// Fused prep: one launch converts x + all weights to fp16 (qkv packed).
// ---------------------------------------------------------------------------
#define U_X   (NTOK * DMODEL / 4)
#define U_W   (DMODEL * DMODEL / 4)
#define U_F   (DMODEL * DFF / 4)
#define U_TOT (U_X + 4 * U_W + 2 * U_F)

__device__ __forceinline__ void cv_lin(const float* in, __half* out, int i) {
    float4 v = *(const float4*)(in + 4 * (size_t)i);
    *(__half2*)(out + 4 * (size_t)i)     = __floats2half2_rn(v.x, v.y);
    *(__half2*)(out + 4 * (size_t)i + 2) = __floats2half2_rn(v.z, v.w);
}
__device__ __forceinline__ void cv_pack(const float* in, __half* out, int i, int off) {
    int row = i >> 8, c4 = (i & 255) * 4;
    float4 v = *(const float4*)(in + (size_t)row * DMODEL + c4);
    __half* o = out + (size_t)row * QLD + off + c4;
    *(__half2*)o       = __floats2half2_rn(v.x, v.y);
    *(__half2*)(o + 2) = __floats2half2_rn(v.z, v.w);
}

__global__ __launch_bounds__(256)
void prep_all_kernel(const float* __restrict__ x,
                     const float* __restrict__ wq, const float* __restrict__ wk,
                     const float* __restrict__ wv, const float* __restrict__ wo,
                     const float* __restrict__ w1, const float* __restrict__ w2,
                     __half* __restrict__ xh, __half* __restrict__ wqkvh,
                     __half* __restrict__ woh, __half* __restrict__ w1h,
                     __half* __restrict__ w2h) {
    int i = blockIdx.x * blockDim.x + threadIdx.x;
    if (i >= U_TOT) return;
    if (i < U_X)            { cv_lin(x, xh, i); return; }
    i -= U_X;
    if (i < U_W)            { cv_pack(wq, wqkvh, i, 0);          return; }
    i -= U_W;
    if (i < U_W)            { cv_pack(wk, wqkvh, i, DMODEL);     return; }
    i -= U_W;
    if (i < U_W)            { cv_pack(wv, wqkvh, i, 2 * DMODEL); return; }
    i -= U_W;
    if (i < U_W)            { cv_lin(wo, woh, i); return; }
    i -= U_W;
    if (i < U_F)            { cv_lin(w1, w1h, i); return; }
    i -= U_F;
    cv_lin(w2, w2h, i);
}

// ---------------------------------------------------------------------------
// FP16 GEMM, ldmatrix fragments, 3-stage cp.async, ONE sync per k-iter.
// C[M,N] = A[M,K] @ B[K,N] (+bias)(+relu). A row-major, B row-major
// (fragments via ldmatrix.trans). 128x128 tile, BK=64, 8 warps.
// ---------------------------------------------------------------------------
#define HLD  72
#define BLD  136
#define HA_H (128 * HLD)
#define HB_H (64 * BLD)
#define HSTAGE_ALL (HA_H + HB_H)
#define HGEMM_SMEM (3 * HSTAGE_ALL * (int)sizeof(__half))

template<bool BIAS, bool RELU, bool HOUT>
__global__ __launch_bounds__(256, 2)
void hgemm(const __half* __restrict__ A, const __half* __restrict__ B,
           const float* __restrict__ bias, void* __restrict__ Cv,
           int M, int N, int K) {
    extern __shared__ __half hsm[];

    const int tid  = threadIdx.x;
    const int lane = tid & 31;
    const int warp = tid >> 5;
    const int wm   = warp & 1;
    const int wn   = warp >> 1;
    const int g    = lane >> 2;
    const int th   = lane & 3;
    const int lrow = lane & 7;
    const int lgrp = lane >> 3;

    const int rowBase = blockIdx.y * 128;
    const int colBase = blockIdx.x * 128;

    float acc[4][4][4];
#pragma unroll
    for (int i = 0; i < 4; i++)
#pragma unroll
        for (int j = 0; j < 4; j++)
#pragma unroll
            for (int r = 0; r < 4; r++) acc[i][j][r] = 0.f;

    uint32_t aoff[4], boff[2];
#pragma unroll
    for (int mt = 0; mt < 4; mt++)
        aoff[mt] = (uint32_t)(((wm * 64 + mt * 16 + (lgrp & 1) * 8 + lrow) * HLD
                               + (lgrp >> 1) * 8) * 2);
#pragma unroll
    for (int p = 0; p < 2; p++)
        boff[p] = (uint32_t)((((lgrp & 1) * 8 + lrow) * BLD
                              + wn * 32 + p * 16 + (lgrp >> 1) * 8) * 2
                             + HA_H * 2);

    auto load_chunk = [&](int c) {
        const int s = c % 3;
        __half* as = hsm + s * HSTAGE_ALL;
        __half* bs = as + HA_H;
        const size_t koff = (size_t)c * 64;
#pragma unroll
        for (int p = 0; p < 4; p++) {
            int idx = tid + p * 256;
            int ra = idx >> 3, ja = (idx & 7) * 8;
            cp_async16(smem_u32(as + ra * HLD + ja),
                       A + (size_t)(rowBase + ra) * K + koff + ja);
            int rb = idx >> 4, jb = (idx & 15) * 8;
            cp_async16(smem_u32(bs + rb * BLD + jb),
                       B + (koff + rb) * N + colBase + jb);
        }
        cp_commit();
    };

    const int nk = K / 64;
    load_chunk(0);
    load_chunk(1);

    for (int it = 0; it < nk; it++) {
        const int s = it % 3;
        if (it + 1 < nk) cp_wait1();     // stage `it` ready; it+1 may fly
        else             cp_wait0();
        __syncthreads();                 // all warps done with stage it-1
        if (it + 2 < nk) load_chunk(it + 2);   // overwrites stage it-1: safe

        const uint32_t sbase = smem_u32(hsm + s * HSTAGE_ALL);
#pragma unroll
        for (int ks = 0; ks < 4; ks++) {
            uint32_t af[4][4], bf[2][4];
#pragma unroll
            for (int mt = 0; mt < 4; mt++)
                ldsm_x4(af[mt], sbase + aoff[mt] + ks * 32);
#pragma unroll
            for (int p = 0; p < 2; p++)
                ldsm_x4_trans(bf[p], sbase + boff[p] + (uint32_t)(ks * 16 * BLD * 2));
#pragma unroll
            for (int mt = 0; mt < 4; mt++) {
                mma_f16(acc[mt][0], af[mt], bf[0][0], bf[0][1]);
                mma_f16(acc[mt][1], af[mt], bf[0][2], bf[0][3]);
                mma_f16(acc[mt][2], af[mt], bf[1][0], bf[1][1]);
                mma_f16(acc[mt][3], af[mt], bf[1][2], bf[1][3]);
            }
        }
    }

    float* Cf = (float*)Cv;
    __half* Ch = (__half*)Cv;
#pragma unroll
    for (int mt = 0; mt < 4; mt++) {
        const int r0 = rowBase + wm * 64 + mt * 16 + g;
#pragma unroll
        for (int nt = 0; nt < 4; nt++) {
            const int c0 = colBase + wn * 32 + nt * 8 + 2 * th;
            float2 v0 = make_float2(acc[mt][nt][0], acc[mt][nt][1]);
            float2 v1 = make_float2(acc[mt][nt][2], acc[mt][nt][3]);
            if (BIAS) {
                float2 bb = *(const float2*)(bias + c0);
                v0.x += bb.x; v0.y += bb.y;
                v1.x += bb.x; v1.y += bb.y;
            }
            if (RELU) {
                v0.x = fmaxf(v0.x, 0.f); v0.y = fmaxf(v0.y, 0.f);
                v1.x = fmaxf(v1.x, 0.f); v1.y = fmaxf(v1.y, 0.f);
            }
            if (HOUT) {
                *(__half2*)(Ch + (size_t)r0 * N + c0)       = __floats2half2_rn(v0.x, v0.y);
                *(__half2*)(Ch + (size_t)(r0 + 8) * N + c0) = __floats2half2_rn(v1.x, v1.y);
            } else {
                *(float2*)(Cf + (size_t)r0 * N + c0)       = v0;
                *(float2*)(Cf + (size_t)(r0 + 8) * N + c0) = v1;
            }
        }
    }
}

// ---------------------------------------------------------------------------
// Flash attention: FP16 mma, P kept in registers (no smem round-trip),
// Q pre-scaled by 1/8 (exact), double-buffered K/V, ONE sync per kv tile.
// Reads packed qkv [tok][3072]: q at +0, k at +1024, v at +2048.
// grid = (SEQ/128, NHEAD, BATCH), 256 threads (8 warps), 16 q-rows per warp.
// smem: K0,V0,K1,V1 = 4 * 64*72 halves = 36,864 B (Q staged in K1/V1 region).
// ---------------------------------------------------------------------------
#define ALD   72
#define ATILE (64 * ALD)
#define AT_SMEM (4 * ATILE * (int)sizeof(__half))

__global__ __launch_bounds__(256)
void flash_attn_h(const __half* __restrict__ qkv, __half* __restrict__ ctx) {
    extern __shared__ __half asm_[];

    const int tid  = threadIdx.x;
    const int lane = tid & 31;
    const int warp = tid >> 5;         // 0..7 -> 16 q rows each
    const int g    = lane >> 2;
    const int th   = lane & 3;
    const int lrow = lane & 7;
    const int lgrp = lane >> 3;
    const int qt   = blockIdx.x;
    const int h    = blockIdx.y;
    const int b    = blockIdx.z;

    const size_t base = (size_t)b * SEQ * QLD + (size_t)h * DK;
    const __half* qp = qkv + base;
    const __half* kp = qkv + base + DMODEL;
    const __half* vp = qkv + base + 2 * DMODEL;

    const int qrow = warp * 16 + g;    // row pair: qrow, qrow+8

    uint32_t koff[4], voff[4];
#pragma unroll
    for (int p = 0; p < 4; p++) {
        koff[p] = (uint32_t)(((p * 16 + (lgrp >> 1) * 8 + lrow) * ALD
                              + (lgrp & 1) * 8) * 2);
        voff[p] = (uint32_t)((((lgrp & 1) * 8 + lrow) * ALD
                              + p * 16 + (lgrp >> 1) * 8) * 2);
    }

    auto load_kv = [&](int kt) {
        __half* kd = asm_ + (kt & 1) * 2 * ATILE;
        __half* vd = kd + ATILE;
#pragma unroll
        for (int i = 0; i < 2; i++) {
            int c = tid + i * 256;              // 0..511
            int r = c >> 3, off = (c & 7) * 8;
            size_t go = (size_t)(kt * 64 + r) * QLD + off;
            cp_async16(smem_u32(kd + r * ALD + off), kp + go);
            cp_async16(smem_u32(vd + r * ALD + off), vp + go);
        }
        cp_commit();
    };
    load_kv(0);                         // -> buffer 0

    // ---- stage Q (pre-scaled by 0.125, exact) into buffer-1 region ----
    __half* Qs = asm_ + 2 * ATILE;      // 128 rows x 72 fits in K1+V1
    const __half2 qsc = __float2half2_rn(0.125f);
    for (int e = tid; e < 128 * 16; e += 256) {
        int r = e >> 4, d4 = (e & 15) * 4;
        uint2 u = *(const uint2*)(qp + (size_t)(qt * 128 + r) * QLD + d4);
        __half2 h0 = __hmul2(*(__half2*)&u.x, qsc);
        __half2 h1 = __hmul2(*(__half2*)&u.y, qsc);
        uint2 w;
        w.x = *(uint32_t*)&h0;
        w.y = *(uint32_t*)&h1;
        *(uint2*)&Qs[r * ALD + d4] = w;
    }
    __syncthreads();

    const uint32_t qoff = (uint32_t)(((warp * 16 + (lgrp & 1) * 8 + lrow) * ALD
                                      + (lgrp >> 1) * 8) * 2);
    uint32_t qf[4][4];
#pragma unroll
    for (int ks = 0; ks < 4; ks++)
        ldsm_x4(qf[ks], smem_u32(Qs) + qoff + ks * 32);

    float m0 = -1e30f, m1 = -1e30f, l0 = 0.f, l1 = 0.f;
    float o[8][4];
#pragma unroll
    for (int i = 0; i < 8; i++)
#pragma unroll
        for (int j = 0; j < 4; j++) o[i][j] = 0.f;

    for (int kt = 0; kt < SEQ / 64; kt++) {
        cp_wait0();                     // KV tile kt landed
        __syncthreads();                // everyone done with buffer kt-1 (and Q ldsm at kt=0)
        if (kt + 1 < SEQ / 64) load_kv(kt + 1);   // overwrites buffer kt-1: safe

        const uint32_t kbase = smem_u32(asm_ + (kt & 1) * 2 * ATILE);
        const uint32_t vbase = kbase + ATILE * 2;   // bytes

        // ---- S = (Q/8) @ K^T ----
        float s[8][4];
#pragma unroll
        for (int nt = 0; nt < 8; nt++)
#pragma unroll
            for (int r = 0; r < 4; r++) s[nt][r] = 0.f;

#pragma unroll
        for (int ks = 0; ks < 4; ks++) {
            const uint32_t k0b = ks * 32;
#pragma unroll
            for (int p = 0; p < 4; p++) {
                uint32_t kf[4];
                ldsm_x4(kf, kbase + koff[p] + k0b);
                mma_f16(s[2 * p],     qf[ks], kf[0], kf[1]);
                mma_f16(s[2 * p + 1], qf[ks], kf[2], kf[3]);
            }
        }

        // ---- online softmax; P packed straight into mma A-fragments ----
        float rm0 = -1e30f, rm1 = -1e30f;
#pragma unroll
        for (int nt = 0; nt < 8; nt++) {
            rm0 = fmaxf(rm0, fmaxf(s[nt][0], s[nt][1]));
            rm1 = fmaxf(rm1, fmaxf(s[nt][2], s[nt][3]));
        }
        rm0 = fmaxf(rm0, __shfl_xor_sync(0xffffffffu, rm0, 1));
        rm0 = fmaxf(rm0, __shfl_xor_sync(0xffffffffu, rm0, 2));
        rm1 = fmaxf(rm1, __shfl_xor_sync(0xffffffffu, rm1, 1));
        rm1 = fmaxf(rm1, __shfl_xor_sync(0xffffffffu, rm1, 2));

        const float mn0 = fmaxf(m0, rm0);
        const float mn1 = fmaxf(m1, rm1);
        const float corr0 = __expf(m0 - mn0);
        const float corr1 = __expf(m1 - mn1);

        uint32_t pf[8][2];              // [nt][0]: rows qrow; [1]: rows qrow+8
        float rs0 = 0.f, rs1 = 0.f;
#pragma unroll
        for (int nt = 0; nt < 8; nt++) {
            float p00 = __expf(s[nt][0] - mn0);
            float p01 = __expf(s[nt][1] - mn0);
            float p10 = __expf(s[nt][2] - mn1);
            float p11 = __expf(s[nt][3] - mn1);
            rs0 += p00 + p01;
            rs1 += p10 + p11;
            __half2 h0 = __floats2half2_rn(p00, p01);
            __half2 h1 = __floats2half2_rn(p10, p11);
            pf[nt][0] = *(uint32_t*)&h0;
            pf[nt][1] = *(uint32_t*)&h1;
        }
        rs0 += __shfl_xor_sync(0xffffffffu, rs0, 1);
        rs0 += __shfl_xor_sync(0xffffffffu, rs0, 2);
        rs1 += __shfl_xor_sync(0xffffffffu, rs1, 1);
        rs1 += __shfl_xor_sync(0xffffffffu, rs1, 2);

        l0 = l0 * corr0 + rs0;
        l1 = l1 * corr1 + rs1;
        m0 = mn0;
        m1 = mn1;

#pragma unroll
        for (int dt = 0; dt < 8; dt++) {
            o[dt][0] *= corr0; o[dt][1] *= corr0;
            o[dt][2] *= corr1; o[dt][3] *= corr1;
        }

        // ---- O += P @ V (A-frags from registers; V via ldmatrix.trans) ----
#pragma unroll
        for (int ks = 0; ks < 4; ks++) {
            uint32_t af[4];
            af[0] = pf[2 * ks][0];
            af[1] = pf[2 * ks][1];
            af[2] = pf[2 * ks + 1][0];
            af[3] = pf[2 * ks + 1][1];
            const uint32_t kvb = (uint32_t)(ks * 16 * ALD * 2);
#pragma unroll
            for (int p = 0; p < 4; p++) {
                uint32_t vf[4];
                ldsm_x4_trans(vf, vbase + voff[p] + kvb);
                mma_f16(o[2 * p],     af, vf[0], vf[1]);
                mma_f16(o[2 * p + 1], af, vf[2], vf[3]);
            }
        }
    }

    // epilogue -> fp16 ctx (stride DMODEL)
    const float inv0 = 1.0f / l0;
    const float inv1 = 1.0f / l1;
    const size_t cbase = (size_t)b * SEQ * DMODEL + (size_t)h * DK;
    const size_t row0 = cbase + (size_t)(qt * 128 + qrow) * DMODEL;
    const size_t row1 = cbase + (size_t)(qt * 128 + qrow + 8) * DMODEL;
#pragma unroll
    for (int dt = 0; dt < 8; dt++) {
        const int c0 = dt * 8 + 2 * th;
        *(__half2*)(ctx + row0 + c0) = __floats2half2_rn(o[dt][0] * inv0, o[dt][1] * inv0);
        *(__half2*)(ctx + row1 + c0) = __floats2half2_rn(o[dt][2] * inv1, o[dt][3] * inv1);
    }
}

// ---------------------------------------------------------------------------
// out = LayerNorm(a + b) * gamma + beta; optional fp16 copy for next GEMM.
// ---------------------------------------------------------------------------
__global__ __launch_bounds__(256)
void add_ln_kernel(const float* __restrict__ a, const float* __restrict__ b,
                   const float* __restrict__ gamma, const float* __restrict__ beta,
                   float* __restrict__ out, __half* __restrict__ out_h) {
    const int row = blockIdx.x;
    const int tid = threadIdx.x;
    const size_t off = (size_t)row * DMODEL;

    __shared__ float r1[8], r2[8];

    float vals[4];
    float sum = 0.f, sq = 0.f;
#pragma unroll
    for (int t = 0; t < 4; t++) {
        int c = tid + t * 256;
        float vv = a[off + c] + b[off + c];
        vals[t] = vv;
        sum += vv;
        sq  += vv * vv;
    }
#pragma unroll
    for (int o = 16; o > 0; o >>= 1) {
        sum += __shfl_xor_sync(0xffffffffu, sum, o);
        sq  += __shfl_xor_sync(0xffffffffu, sq,  o);
    }
    const int wid = tid >> 5;
    if ((tid & 31) == 0) { r1[wid] = sum; r2[wid] = sq; }
    __syncthreads();
    float tot1 = 0.f, tot2 = 0.f;
#pragma unroll
    for (int w = 0; w < 8; w++) { tot1 += r1[w]; tot2 += r2[w]; }

    const float mu   = tot1 * (1.0f / DMODEL);
    const float var  = tot2 * (1.0f / DMODEL) - mu * mu;
    const float rstd = rsqrtf(var + LN_EPS);

#pragma unroll
    for (int t = 0; t < 4; t++) {
        int c = tid + t * 256;
        float y = (vals[t] - mu) * rstd * gamma[c] + beta[c];
        out[off + c] = y;
        if (out_h) out_h[off + c] = __float2half(y);
    }
}

// ---------------------------------------------------------------------------
// Launcher
// ---------------------------------------------------------------------------
extern "C" void kernel_launch(void* const* d_in, const int* in_sizes, int n_in,
                              void* d_out, int out_size) {
    (void)in_sizes; (void)n_in; (void)out_size;
    const float* x   = (const float*)d_in[0];
    const float* wq  = (const float*)d_in[1];
    const float* wk  = (const float*)d_in[2];
    const float* wv  = (const float*)d_in[3];
    const float* wo  = (const float*)d_in[4];
    const float* w1  = (const float*)d_in[5];
    const float* b1  = (const float*)d_in[6];
    const float* w2  = (const float*)d_in[7];
    const float* b2  = (const float*)d_in[8];
    const float* g1  = (const float*)d_in[9];
    const float* be1 = (const float*)d_in[10];
    const float* g2  = (const float*)d_in[11];
    const float* be2 = (const float*)d_in[12];
    float* out = (float*)d_out;

    __half *xh, *qkvh, *ctxh, *hrh, *ffh, *wqkvh, *woh, *w1h, *w2h;
    float *attn, *h, *f2;
    cudaGetSymbolAddress((void**)&xh,    g_xh);
    cudaGetSymbolAddress((void**)&qkvh,  g_qkvh);
    cudaGetSymbolAddress((void**)&ctxh,  g_ctxh);
    cudaGetSymbolAddress((void**)&hrh,   g_hrh);
    cudaGetSymbolAddress((void**)&ffh,   g_ffh);
    cudaGetSymbolAddress((void**)&attn,  g_attn);
    cudaGetSymbolAddress((void**)&h,     g_h);
    cudaGetSymbolAddress((void**)&f2,    g_f2);
    cudaGetSymbolAddress((void**)&wqkvh, g_wqkvh);
    cudaGetSymbolAddress((void**)&woh,   g_woh);
    cudaGetSymbolAddress((void**)&w1h,   g_w1h);
    cudaGetSymbolAddress((void**)&w2h,   g_w2h);

    cudaFuncSetAttribute(hgemm<false, false, true>,
                         cudaFuncAttributeMaxDynamicSharedMemorySize, HGEMM_SMEM);
    cudaFuncSetAttribute(hgemm<false, false, false>,
                         cudaFuncAttributeMaxDynamicSharedMemorySize, HGEMM_SMEM);
    cudaFuncSetAttribute(hgemm<true, true, true>,
                         cudaFuncAttributeMaxDynamicSharedMemorySize, HGEMM_SMEM);
    cudaFuncSetAttribute(hgemm<true, false, false>,
                         cudaFuncAttributeMaxDynamicSharedMemorySize, HGEMM_SMEM);
    cudaFuncSetAttribute(flash_attn_h,
                         cudaFuncAttributeMaxDynamicSharedMemorySize, AT_SMEM);

    // ---- fused prep: one launch converts everything to fp16 ----
    prep_all_kernel<<<(U_TOT + 255) / 256, 256>>>(x, wq, wk, wv, wo, w1, w2,
                                                  xh, wqkvh, woh, w1h, w2h);

    const dim3 g_qkv(QLD / 128,    NTOK / 128);   // (24, 64)
    const dim3 g_dd (DMODEL / 128, NTOK / 128);   // (8, 64)
    const dim3 g_df (DFF / 128,    NTOK / 128);   // (32, 64)

    // fused QKV projection -> packed fp16 [tok][3072]
    hgemm<false, false, true><<<g_qkv, 256, HGEMM_SMEM>>>(xh, wqkvh, nullptr, qkvh,
                                                          NTOK, QLD, DMODEL);

    // attention -> fp16 ctx
    flash_attn_h<<<dim3(SEQ / 128, NHEAD, BATCH), 256, AT_SMEM>>>(qkvh, ctxh);

    // output projection -> fp32
    hgemm<false, false, false><<<g_dd, 256, HGEMM_SMEM>>>(ctxh, woh, nullptr, attn,
                                                          NTOK, DMODEL, DMODEL);

    // add & norm 1 (h fp32 residual, hrh fp16 for FFN1)
    add_ln_kernel<<<NTOK, 256>>>(x, attn, g1, be1, h, hrh);

    // FFN
    hgemm<true, true,  true ><<<g_df, 256, HGEMM_SMEM>>>(hrh, w1h, b1, ffh, NTOK, DFF,    DMODEL);
    hgemm<true, false, false><<<g_dd, 256, HGEMM_SMEM>>>(ffh, w2h, b2, f2,  NTOK, DMODEL, DFF);

    // add & norm 2
    add_ln_kernel<<<NTOK, 256>>>(h, f2, g2, be2, out, nullptr);
}

// round 17
// speedup vs baseline: 1.0850x; 1.0132x over previous
#include <cuda_runtime.h>
#include <cuda_fp16.h>
#include <math.h>
#include <stdint.h>

// ---------------------------------------------------------------------------
// Problem constants
// ---------------------------------------------------------------------------
#define BATCH   4
#define SEQ     2048
#define DMODEL  1024
#define NHEAD   16
#define DK      64
#define DFF     4096
#define NTOK    (BATCH * SEQ)          // 8192
#define LN_EPS  1e-5f
#define QLD     (3 * DMODEL)           // packed qkv row stride

// ---------------------------------------------------------------------------
// Scratch (device globals — allocation-free rule)
// ---------------------------------------------------------------------------
__device__ __half g_xh   [NTOK * DMODEL];
__device__ __half g_qkvh [NTOK * QLD];
__device__ __half g_ctxh [NTOK * DMODEL];
__device__ __half g_hrh  [NTOK * DMODEL];
__device__ __half g_ffh  [NTOK * DFF];
__device__ float  g_attn [NTOK * DMODEL];
__device__ float  g_h    [NTOK * DMODEL];
__device__ float  g_f2   [NTOK * DMODEL];
// fp16 ROW-MAJOR weights: wh[k][n] = (half)w[k][n]
__device__ __half g_wqkvh[DMODEL * QLD];
__device__ __half g_woh  [DMODEL * DMODEL];
__device__ __half g_w1h  [DMODEL * DFF];
__device__ __half g_w2h  [DFF * DMODEL];

// ---------------------------------------------------------------------------
// Helpers
// ---------------------------------------------------------------------------
__device__ __forceinline__ uint32_t smem_u32(const void* p) {
    return (uint32_t)__cvta_generic_to_shared(p);
}
__device__ __forceinline__ void cp_async16(uint32_t dst, const void* src) {
    asm volatile("cp.async.cg.shared.global [%0], [%1], 16;\n" :: "r"(dst), "l"(src));
}
__device__ __forceinline__ void cp_commit() { asm volatile("cp.async.commit_group;\n"); }
__device__ __forceinline__ void cp_wait1()  { asm volatile("cp.async.wait_group 1;\n"); }
__device__ __forceinline__ void cp_wait0()  { asm volatile("cp.async.wait_group 0;\n"); }

// mma.m16n8k16 row.col f32 += f16 * f16
__device__ __forceinline__ void mma_f16(float* c, const uint32_t* a,
                                        uint32_t b0, uint32_t b1) {
    asm volatile(
        "mma.sync.aligned.m16n8k16.row.col.f32.f16.f16.f32 "
        "{%0,%1,%2,%3}, {%4,%5,%6,%7}, {%8,%9}, {%0,%1,%2,%3};"
        : "+f"(c[0]), "+f"(c[1]), "+f"(c[2]), "+f"(c[3])
        : "r"(a[0]), "r"(a[1]), "r"(a[2]), "r"(a[3]), "r"(b0), "r"(b1));
}

__device__ __forceinline__ void ldsm_x4(uint32_t* r, uint32_t addr) {
    asm volatile("ldmatrix.sync.aligned.m8n8.x4.shared.b16 {%0,%1,%2,%3}, [%4];"
                 : "=r"(r[0]), "=r"(r[1]), "=r"(r[2]), "=r"(r[3]) : "r"(addr));
}
__device__ __forceinline__ void ldsm_x4_trans(uint32_t* r, uint32_t addr) {
    asm volatile("ldmatrix.sync.aligned.m8n8.x4.trans.shared.b16 {%0,%1,%2,%3}, [%4];"
                 : "=r"(r[0]), "=r"(r[1]), "=r"(r[2]), "=r"(r[3]) : "r"(addr));
}

// ---------------------------------------------------------------------------
// Fused prep: one launch converts x + all weights to fp16 (qkv packed).
// ---------------------------------------------------------------------------
#define U_X   (NTOK * DMODEL / 4)
#define U_W   (DMODEL * DMODEL / 4)
#define U_F   (DMODEL * DFF / 4)
#define U_TOT (U_X + 4 * U_W + 2 * U_F)

__device__ __forceinline__ void cv_lin(const float* in, __half* out, int i) {
    float4 v = *(const float4*)(in + 4 * (size_t)i);
    *(__half2*)(out + 4 * (size_t)i)     = __floats2half2_rn(v.x, v.y);
    *(__half2*)(out + 4 * (size_t)i + 2) = __floats2half2_rn(v.z, v.w);
}
__device__ __forceinline__ void cv_pack(const float* in, __half* out, int i, int off) {
    int row = i >> 8, c4 = (i & 255) * 4;
    float4 v = *(const float4*)(in + (size_t)row * DMODEL + c4);
    __half* o = out + (size_t)row * QLD + off + c4;
    *(__half2*)o       = __floats2half2_rn(v.x, v.y);
    *(__half2*)(o + 2) = __floats2half2_rn(v.z, v.w);
}

__global__ __launch_bounds__(256)
void prep_all_kernel(const float* __restrict__ x,
                     const float* __restrict__ wq, const float* __restrict__ wk,
                     const float* __restrict__ wv, const float* __restrict__ wo,
                     const float* __restrict__ w1, const float* __restrict__ w2,
                     __half* __restrict__ xh, __half* __restrict__ wqkvh,
                     __half* __restrict__ woh, __half* __restrict__ w1h,
                     __half* __restrict__ w2h) {
    int i = blockIdx.x * blockDim.x + threadIdx.x;
    if (i >= U_TOT) return;
    if (i < U_X)            { cv_lin(x, xh, i); return; }
    i -= U_X;
    if (i < U_W)            { cv_pack(wq, wqkvh, i, 0);          return; }
    i -= U_W;
    if (i < U_W)            { cv_pack(wk, wqkvh, i, DMODEL);     return; }
    i -= U_W;
    if (i < U_W)            { cv_pack(wv, wqkvh, i, 2 * DMODEL); return; }
    i -= U_W;
    if (i < U_W)            { cv_lin(wo, woh, i); return; }
    i -= U_W;
    if (i < U_F)            { cv_lin(w1, w1h, i); return; }
    i -= U_F;
    cv_lin(w2, w2h, i);
}

// ---------------------------------------------------------------------------
// FP16 GEMM variant A (R9): 128x128 tile, BK=64, 8 warps, 3-stage cp.async.
// For large-grid GEMMs (QKV, FFN1).
// ---------------------------------------------------------------------------
#define HLD  72
#define BLD  136
#define HA_H (128 * HLD)
#define HB_H (64 * BLD)
#define HSTAGE_ALL (HA_H + HB_H)
#define HGEMM_SMEM (3 * HSTAGE_ALL * (int)sizeof(__half))

template<bool BIAS, bool RELU, bool HOUT>
__global__ __launch_bounds__(256, 2)
void hgemm(const __half* __restrict__ A, const __half* __restrict__ B,
           const float* __restrict__ bias, void* __restrict__ Cv,
           int M, int N, int K) {
    extern __shared__ __half hsm[];

    const int tid  = threadIdx.x;
    const int lane = tid & 31;
    const int warp = tid >> 5;
    const int wm   = warp & 1;
    const int wn   = warp >> 1;
    const int g    = lane >> 2;
    const int th   = lane & 3;
    const int lrow = lane & 7;
    const int lgrp = lane >> 3;

    const int rowBase = blockIdx.y * 128;
    const int colBase = blockIdx.x * 128;

    float acc[4][4][4];
#pragma unroll
    for (int i = 0; i < 4; i++)
#pragma unroll
        for (int j = 0; j < 4; j++)
#pragma unroll
            for (int r = 0; r < 4; r++) acc[i][j][r] = 0.f;

    uint32_t aoff[4], boff[2];
#pragma unroll
    for (int mt = 0; mt < 4; mt++)
        aoff[mt] = (uint32_t)(((wm * 64 + mt * 16 + (lgrp & 1) * 8 + lrow) * HLD
                               + (lgrp >> 1) * 8) * 2);
#pragma unroll
    for (int p = 0; p < 2; p++)
        boff[p] = (uint32_t)((((lgrp & 1) * 8 + lrow) * BLD
                              + wn * 32 + p * 16 + (lgrp >> 1) * 8) * 2
                             + HA_H * 2);

    auto load_chunk = [&](int c) {
        const int s = c % 3;
        __half* as = hsm + s * HSTAGE_ALL;
        __half* bs = as + HA_H;
        const size_t koff = (size_t)c * 64;
#pragma unroll
        for (int p = 0; p < 4; p++) {
            int idx = tid + p * 256;
            int ra = idx >> 3, ja = (idx & 7) * 8;
            cp_async16(smem_u32(as + ra * HLD + ja),
                       A + (size_t)(rowBase + ra) * K + koff + ja);
            int rb = idx >> 4, jb = (idx & 15) * 8;
            cp_async16(smem_u32(bs + rb * BLD + jb),
                       B + (koff + rb) * N + colBase + jb);
        }
        cp_commit();
    };

    const int nk = K / 64;
    load_chunk(0);
    load_chunk(1);

    for (int it = 0; it < nk; it++) {
        const int s = it % 3;
        if (it + 1 < nk) cp_wait1();
        else             cp_wait0();
        __syncthreads();
        if (it + 2 < nk) load_chunk(it + 2);

        const uint32_t sbase = smem_u32(hsm + s * HSTAGE_ALL);
#pragma unroll
        for (int ks = 0; ks < 4; ks++) {
            uint32_t af[4][4], bf[2][4];
#pragma unroll
            for (int mt = 0; mt < 4; mt++)
                ldsm_x4(af[mt], sbase + aoff[mt] + ks * 32);
#pragma unroll
            for (int p = 0; p < 2; p++)
                ldsm_x4_trans(bf[p], sbase + boff[p] + (uint32_t)(ks * 16 * BLD * 2));
#pragma unroll
            for (int mt = 0; mt < 4; mt++) {
                mma_f16(acc[mt][0], af[mt], bf[0][0], bf[0][1]);
                mma_f16(acc[mt][1], af[mt], bf[0][2], bf[0][3]);
                mma_f16(acc[mt][2], af[mt], bf[1][0], bf[1][1]);
                mma_f16(acc[mt][3], af[mt], bf[1][2], bf[1][3]);
            }
        }
    }

    float* Cf = (float*)Cv;
    __half* Ch = (__half*)Cv;
#pragma unroll
    for (int mt = 0; mt < 4; mt++) {
        const int r0 = rowBase + wm * 64 + mt * 16 + g;
#pragma unroll
        for (int nt = 0; nt < 4; nt++) {
            const int c0 = colBase + wn * 32 + nt * 8 + 2 * th;
            float2 v0 = make_float2(acc[mt][nt][0], acc[mt][nt][1]);
            float2 v1 = make_float2(acc[mt][nt][2], acc[mt][nt][3]);
            if (BIAS) {
                float2 bb = *(const float2*)(bias + c0);
                v0.x += bb.x; v0.y += bb.y;
                v1.x += bb.x; v1.y += bb.y;
            }
            if (RELU) {
                v0.x = fmaxf(v0.x, 0.f); v0.y = fmaxf(v0.y, 0.f);
                v1.x = fmaxf(v1.x, 0.f); v1.y = fmaxf(v1.y, 0.f);
            }
            if (HOUT) {
                *(__half2*)(Ch + (size_t)r0 * N + c0)       = __floats2half2_rn(v0.x, v0.y);
                *(__half2*)(Ch + (size_t)(r0 + 8) * N + c0) = __floats2half2_rn(v1.x, v1.y);
            } else {
                *(float2*)(Cf + (size_t)r0 * N + c0)       = v0;
                *(float2*)(Cf + (size_t)(r0 + 8) * N + c0) = v1;
            }
        }
    }
}

// ---------------------------------------------------------------------------
// FP16 GEMM variant B (R11): 64x128 tile, BK=64, 8 warps, warp tile 32x32,
// 2-stage cp.async, 3 CTAs/SM. For tail-bound 512-CTA shapes (Wo, FFN2).
// smem/stage: A 64x72 + B 64x136 halves = 26,624 B; 2 stages = 53,248 B.
// ---------------------------------------------------------------------------
#define SA_H (64 * HLD)
#define SSTAGE_ALL (SA_H + HB_H)
#define SGEMM_SMEM (2 * SSTAGE_ALL * (int)sizeof(__half))

template<bool BIAS, bool RELU, bool HOUT>
__global__ __launch_bounds__(256, 3)
void hgemm64(const __half* __restrict__ A, const __half* __restrict__ B,
             const float* __restrict__ bias, void* __restrict__ Cv,
             int M, int N, int K) {
    extern __shared__ __half hsm[];

    const int tid  = threadIdx.x;
    const int lane = tid & 31;
    const int warp = tid >> 5;
    const int wm   = warp & 1;        // 32-row half of 64
    const int wn   = warp >> 1;       // 32-col quarter of 128
    const int g    = lane >> 2;
    const int th   = lane & 3;
    const int lrow = lane & 7;
    const int lgrp = lane >> 3;

    const int rowBase = blockIdx.y * 64;
    const int colBase = blockIdx.x * 128;

    float acc[2][4][4];
#pragma unroll
    for (int i = 0; i < 2; i++)
#pragma unroll
        for (int j = 0; j < 4; j++)
#pragma unroll
            for (int r = 0; r < 4; r++) acc[i][j][r] = 0.f;

    uint32_t aoff[2], boff[2];
#pragma unroll
    for (int mt = 0; mt < 2; mt++)
        aoff[mt] = (uint32_t)(((wm * 32 + mt * 16 + (lgrp & 1) * 8 + lrow) * HLD
                               + (lgrp >> 1) * 8) * 2);
#pragma unroll
    for (int p = 0; p < 2; p++)
        boff[p] = (uint32_t)((((lgrp & 1) * 8 + lrow) * BLD
                              + wn * 32 + p * 16 + (lgrp >> 1) * 8) * 2
                             + SA_H * 2);

    auto load_chunk = [&](int c) {
        const int s = c & 1;
        __half* as = hsm + s * SSTAGE_ALL;
        __half* bs = as + SA_H;
        const size_t koff = (size_t)c * 64;
#pragma unroll
        for (int p = 0; p < 2; p++) {
            int idx = tid + p * 256;
            int ra = idx >> 3, ja = (idx & 7) * 8;
            cp_async16(smem_u32(as + ra * HLD + ja),
                       A + (size_t)(rowBase + ra) * K + koff + ja);
        }
#pragma unroll
        for (int p = 0; p < 4; p++) {
            int idx = tid + p * 256;
            int rb = idx >> 4, jb = (idx & 15) * 8;
            cp_async16(smem_u32(bs + rb * BLD + jb),
                       B + (koff + rb) * N + colBase + jb);
        }
        cp_commit();
    };

    const int nk = K / 64;
    load_chunk(0);

    for (int it = 0; it < nk; it++) {
        cp_wait0();
        __syncthreads();
        if (it + 1 < nk) load_chunk(it + 1);

        const uint32_t sbase = smem_u32(hsm + (it & 1) * SSTAGE_ALL);
#pragma unroll
        for (int ks = 0; ks < 4; ks++) {
            uint32_t af[2][4], bf[2][4];
#pragma unroll
            for (int mt = 0; mt < 2; mt++)
                ldsm_x4(af[mt], sbase + aoff[mt] + ks * 32);
#pragma unroll
            for (int p = 0; p < 2; p++)
                ldsm_x4_trans(bf[p], sbase + boff[p] + (uint32_t)(ks * 16 * BLD * 2));
#pragma unroll
            for (int mt = 0; mt < 2; mt++) {
                mma_f16(acc[mt][0], af[mt], bf[0][0], bf[0][1]);
                mma_f16(acc[mt][1], af[mt], bf[0][2], bf[0][3]);
                mma_f16(acc[mt][2], af[mt], bf[1][0], bf[1][1]);
                mma_f16(acc[mt][3], af[mt], bf[1][2], bf[1][3]);
            }
        }
    }

    float* Cf = (float*)Cv;
    __half* Ch = (__half*)Cv;
#pragma unroll
    for (int mt = 0; mt < 2; mt++) {
        const int r0 = rowBase + wm * 32 + mt * 16 + g;
#pragma unroll
        for (int nt = 0; nt < 4; nt++) {
            const int c0 = colBase + wn * 32 + nt * 8 + 2 * th;
            float2 v0 = make_float2(acc[mt][nt][0], acc[mt][nt][1]);
            float2 v1 = make_float2(acc[mt][nt][2], acc[mt][nt][3]);
            if (BIAS) {
                float2 bb = *(const float2*)(bias + c0);
                v0.x += bb.x; v0.y += bb.y;
                v1.x += bb.x; v1.y += bb.y;
            }
            if (RELU) {
                v0.x = fmaxf(v0.x, 0.f); v0.y = fmaxf(v0.y, 0.f);
                v1.x = fmaxf(v1.x, 0.f); v1.y = fmaxf(v1.y, 0.f);
            }
            if (HOUT) {
                *(__half2*)(Ch + (size_t)r0 * N + c0)       = __floats2half2_rn(v0.x, v0.y);
                *(__half2*)(Ch + (size_t)(r0 + 8) * N + c0) = __floats2half2_rn(v1.x, v1.y);
            } else {
                *(float2*)(Cf + (size_t)r0 * N + c0)       = v0;
                *(float2*)(Cf + (size_t)(r0 + 8) * N + c0) = v1;
            }
        }
    }
}

// ---------------------------------------------------------------------------
// Flash attention (exact R9 form): FP16 mma, P in registers, Q pre-scaled by
// 0.125 (exact), __expf softmax, double-buffered K/V tiles.
// grid = (SEQ/128, NHEAD, BATCH), 256 threads (8 warps), 16 q-rows per warp.
// smem: K0,V0,K1,V1 = 4 * 64*72 halves = 36,864 B.
// ---------------------------------------------------------------------------
#define ALD   72
#define ATILE (64 * ALD)
#define AT_SMEM (4 * ATILE * (int)sizeof(__half))

__global__ __launch_bounds__(256)
void flash_attn_h(const __half* __restrict__ qkv, __half* __restrict__ ctx) {
    extern __shared__ __half asm_[];

    const int tid  = threadIdx.x;
    const int lane = tid & 31;
    const int warp = tid >> 5;
    const int g    = lane >> 2;
    const int th   = lane & 3;
    const int lrow = lane & 7;
    const int lgrp = lane >> 3;
    const int qt   = blockIdx.x;
    const int h    = blockIdx.y;
    const int b    = blockIdx.z;

    const size_t base = (size_t)b * SEQ * QLD + (size_t)h * DK;
    const __half* qp = qkv + base;
    const __half* kp = qkv + base + DMODEL;
    const __half* vp = qkv + base + 2 * DMODEL;

    const int qrow = warp * 16 + g;

    uint32_t koff[4], voff[4];
#pragma unroll
    for (int p = 0; p < 4; p++) {
        koff[p] = (uint32_t)(((p * 16 + (lgrp >> 1) * 8 + lrow) * ALD
                              + (lgrp & 1) * 8) * 2);
        voff[p] = (uint32_t)((((lgrp & 1) * 8 + lrow) * ALD
                              + p * 16 + (lgrp >> 1) * 8) * 2);
    }

    auto load_kv = [&](int kt) {
        __half* kd = asm_ + (kt & 1) * 2 * ATILE;
        __half* vd = kd + ATILE;
#pragma unroll
        for (int i = 0; i < 2; i++) {
            int c = tid + i * 256;
            int r = c >> 3, off = (c & 7) * 8;
            size_t go = (size_t)(kt * 64 + r) * QLD + off;
            cp_async16(smem_u32(kd + r * ALD + off), kp + go);
            cp_async16(smem_u32(vd + r * ALD + off), vp + go);
        }
        cp_commit();
    };
    load_kv(0);

    // ---- stage Q (pre-scaled by 0.125, exact) into buffer-1 region ----
    __half* Qs = asm_ + 2 * ATILE;
    const __half2 qsc = __float2half2_rn(0.125f);
    for (int e = tid; e < 128 * 16; e += 256) {
        int r = e >> 4, d4 = (e & 15) * 4;
        uint2 u = *(const uint2*)(qp + (size_t)(qt * 128 + r) * QLD + d4);
        __half2 h0 = __hmul2(*(__half2*)&u.x, qsc);
        __half2 h1 = __hmul2(*(__half2*)&u.y, qsc);
        uint2 w;
        w.x = *(uint32_t*)&h0;
        w.y = *(uint32_t*)&h1;
        *(uint2*)&Qs[r * ALD + d4] = w;
    }
    __syncthreads();

    const uint32_t qoff = (uint32_t)(((warp * 16 + (lgrp & 1) * 8 + lrow) * ALD
                                      + (lgrp >> 1) * 8) * 2);
    uint32_t qf[4][4];
#pragma unroll
    for (int ks = 0; ks < 4; ks++)
        ldsm_x4(qf[ks], smem_u32(Qs) + qoff + ks * 32);

    float m0 = -1e30f, m1 = -1e30f, l0 = 0.f, l1 = 0.f;
    float o[8][4];
#pragma unroll
    for (int i = 0; i < 8; i++)
#pragma unroll
        for (int j = 0; j < 4; j++) o[i][j] = 0.f;

    for (int kt = 0; kt < SEQ / 64; kt++) {
        cp_wait0();
        __syncthreads();
        if (kt + 1 < SEQ / 64) load_kv(kt + 1);

        const uint32_t kbase = smem_u32(asm_ + (kt & 1) * 2 * ATILE);
        const uint32_t vbase = kbase + ATILE * 2;

        // ---- S = (Q/8) @ K^T ----
        float s[8][4];
#pragma unroll
        for (int nt = 0; nt < 8; nt++)
#pragma unroll
            for (int r = 0; r < 4; r++) s[nt][r] = 0.f;

#pragma unroll
        for (int ks = 0; ks < 4; ks++) {
            const uint32_t k0b = ks * 32;
#pragma unroll
            for (int p = 0; p < 4; p++) {
                uint32_t kf[4];
                ldsm_x4(kf, kbase + koff[p] + k0b);
                mma_f16(s[2 * p],     qf[ks], kf[0], kf[1]);
                mma_f16(s[2 * p + 1], qf[ks], kf[2], kf[3]);
            }
        }

        // ---- online softmax; P packed straight into mma A-fragments ----
        float rm0 = -1e30f, rm1 = -1e30f;
#pragma unroll
        for (int nt = 0; nt < 8; nt++) {
            rm0 = fmaxf(rm0, fmaxf(s[nt][0], s[nt][1]));
            rm1 = fmaxf(rm1, fmaxf(s[nt][2], s[nt][3]));
        }
        rm0 = fmaxf(rm0, __shfl_xor_sync(0xffffffffu, rm0, 1));
        rm0 = fmaxf(rm0, __shfl_xor_sync(0xffffffffu, rm0, 2));
        rm1 = fmaxf(rm1, __shfl_xor_sync(0xffffffffu, rm1, 1));
        rm1 = fmaxf(rm1, __shfl_xor_sync(0xffffffffu, rm1, 2));

        const float mn0 = fmaxf(m0, rm0);
        const float mn1 = fmaxf(m1, rm1);
        const float corr0 = __expf(m0 - mn0);
        const float corr1 = __expf(m1 - mn1);

        uint32_t pf[8][2];
        float rs0 = 0.f, rs1 = 0.f;
#pragma unroll
        for (int nt = 0; nt < 8; nt++) {
            float p00 = __expf(s[nt][0] - mn0);
            float p01 = __expf(s[nt][1] - mn0);
            float p10 = __expf(s[nt][2] - mn1);
            float p11 = __expf(s[nt][3] - mn1);
            rs0 += p00 + p01;
            rs1 += p10 + p11;
            __half2 h0 = __floats2half2_rn(p00, p01);
            __half2 h1 = __floats2half2_rn(p10, p11);
            pf[nt][0] = *(uint32_t*)&h0;
            pf[nt][1] = *(uint32_t*)&h1;
        }
        rs0 += __shfl_xor_sync(0xffffffffu, rs0, 1);
        rs0 += __shfl_xor_sync(0xffffffffu, rs0, 2);
        rs1 += __shfl_xor_sync(0xffffffffu, rs1, 1);
        rs1 += __shfl_xor_sync(0xffffffffu, rs1, 2);

        l0 = l0 * corr0 + rs0;
        l1 = l1 * corr1 + rs1;
        m0 = mn0;
        m1 = mn1;

#pragma unroll
        for (int dt = 0; dt < 8; dt++) {
            o[dt][0] *= corr0; o[dt][1] *= corr0;
            o[dt][2] *= corr1; o[dt][3] *= corr1;
        }

        // ---- O += P @ V (A-frags from registers; V via ldmatrix.trans) ----
#pragma unroll
        for (int ks = 0; ks < 4; ks++) {
            uint32_t af[4];
            af[0] = pf[2 * ks][0];
            af[1] = pf[2 * ks][1];
            af[2] = pf[2 * ks + 1][0];
            af[3] = pf[2 * ks + 1][1];
            const uint32_t kvb = (uint32_t)(ks * 16 * ALD * 2);
#pragma unroll
            for (int p = 0; p < 4; p++) {
                uint32_t vf[4];
                ldsm_x4_trans(vf, vbase + voff[p] + kvb);
                mma_f16(o[2 * p],     af, vf[0], vf[1]);
                mma_f16(o[2 * p + 1], af, vf[2], vf[3]);
            }
        }
    }

    // epilogue -> fp16 ctx (stride DMODEL)
    const float inv0 = 1.0f / l0;
    const float inv1 = 1.0f / l1;
    const size_t cbase = (size_t)b * SEQ * DMODEL + (size_t)h * DK;
    const size_t row0 = cbase + (size_t)(qt * 128 + qrow) * DMODEL;
    const size_t row1 = cbase + (size_t)(qt * 128 + qrow + 8) * DMODEL;
#pragma unroll
    for (int dt = 0; dt < 8; dt++) {
        const int c0 = dt * 8 + 2 * th;
        *(__half2*)(ctx + row0 + c0) = __floats2half2_rn(o[dt][0] * inv0, o[dt][1] * inv0);
        *(__half2*)(ctx + row1 + c0) = __floats2half2_rn(o[dt][2] * inv1, o[dt][3] * inv1);
    }
}

// ---------------------------------------------------------------------------
// out = LayerNorm(a + b) * gamma + beta; optional fp16 copy for next GEMM.
// ---------------------------------------------------------------------------
__global__ __launch_bounds__(256)
void add_ln_kernel(const float* __restrict__ a, const float* __restrict__ b,
                   const float* __restrict__ gamma, const float* __restrict__ beta,
                   float* __restrict__ out, __half* __restrict__ out_h) {
    const int row = blockIdx.x;
    const int tid = threadIdx.x;
    const size_t off = (size_t)row * DMODEL;

    __shared__ float r1[8], r2[8];

    float vals[4];
    float sum = 0.f, sq = 0.f;
#pragma unroll
    for (int t = 0; t < 4; t++) {
        int c = tid + t * 256;
        float vv = a[off + c] + b[off + c];
        vals[t] = vv;
        sum += vv;
        sq  += vv * vv;
    }
#pragma unroll
    for (int o = 16; o > 0; o >>= 1) {
        sum += __shfl_xor_sync(0xffffffffu, sum, o);
        sq  += __shfl_xor_sync(0xffffffffu, sq,  o);
    }
    const int wid = tid >> 5;
    if ((tid & 31) == 0) { r1[wid] = sum; r2[wid] = sq; }
    __syncthreads();
    float tot1 = 0.f, tot2 = 0.f;
#pragma unroll
    for (int w = 0; w < 8; w++) { tot1 += r1[w]; tot2 += r2[w]; }

    const float mu   = tot1 * (1.0f / DMODEL);
    const float var  = tot2 * (1.0f / DMODEL) - mu * mu;
    const float rstd = rsqrtf(var + LN_EPS);

#pragma unroll
    for (int t = 0; t < 4; t++) {
        int c = tid + t * 256;
        float y = (vals[t] - mu) * rstd * gamma[c] + beta[c];
        out[off + c] = y;
        if (out_h) out_h[off + c] = __float2half(y);
    }
}

// ---------------------------------------------------------------------------
// Launcher
// ---------------------------------------------------------------------------
extern "C" void kernel_launch(void* const* d_in, const int* in_sizes, int n_in,
                              void* d_out, int out_size) {
    (void)in_sizes; (void)n_in; (void)out_size;
    const float* x   = (const float*)d_in[0];
    const float* wq  = (const float*)d_in[1];
    const float* wk  = (const float*)d_in[2];
    const float* wv  = (const float*)d_in[3];
    const float* wo  = (const float*)d_in[4];
    const float* w1  = (const float*)d_in[5];
    const float* b1  = (const float*)d_in[6];
    const float* w2  = (const float*)d_in[7];
    const float* b2  = (const float*)d_in[8];
    const float* g1  = (const float*)d_in[9];
    const float* be1 = (const float*)d_in[10];
    const float* g2  = (const float*)d_in[11];
    const float* be2 = (const float*)d_in[12];
    float* out = (float*)d_out;

    __half *xh, *qkvh, *ctxh, *hrh, *ffh, *wqkvh, *woh, *w1h, *w2h;
    float *attn, *h, *f2;
    cudaGetSymbolAddress((void**)&xh,    g_xh);
    cudaGetSymbolAddress((void**)&qkvh,  g_qkvh);
    cudaGetSymbolAddress((void**)&ctxh,  g_ctxh);
    cudaGetSymbolAddress((void**)&hrh,   g_hrh);
    cudaGetSymbolAddress((void**)&ffh,   g_ffh);
    cudaGetSymbolAddress((void**)&attn,  g_attn);
    cudaGetSymbolAddress((void**)&h,     g_h);
    cudaGetSymbolAddress((void**)&f2,    g_f2);
    cudaGetSymbolAddress((void**)&wqkvh, g_wqkvh);
    cudaGetSymbolAddress((void**)&woh,   g_woh);
    cudaGetSymbolAddress((void**)&w1h,   g_w1h);
    cudaGetSymbolAddress((void**)&w2h,   g_w2h);

    cudaFuncSetAttribute(hgemm<false, false, true>,
                         cudaFuncAttributeMaxDynamicSharedMemorySize, HGEMM_SMEM);
    cudaFuncSetAttribute(hgemm<true, true, true>,
                         cudaFuncAttributeMaxDynamicSharedMemorySize, HGEMM_SMEM);
    cudaFuncSetAttribute(hgemm64<false, false, false>,
                         cudaFuncAttributeMaxDynamicSharedMemorySize, SGEMM_SMEM);
    cudaFuncSetAttribute(hgemm64<true, false, false>,
                         cudaFuncAttributeMaxDynamicSharedMemorySize, SGEMM_SMEM);
    cudaFuncSetAttribute(flash_attn_h,
                         cudaFuncAttributeMaxDynamicSharedMemorySize, AT_SMEM);

    // ---- fused prep: one launch converts everything to fp16 ----
    prep_all_kernel<<<(U_TOT + 255) / 256, 256>>>(x, wq, wk, wv, wo, w1, w2,
                                                  xh, wqkvh, woh, w1h, w2h);

    const dim3 g_qkv (QLD / 128,    NTOK / 128);   // (24, 64)  128x128 tiles
    const dim3 g_df  (DFF / 128,    NTOK / 128);   // (32, 64)  128x128 tiles
    const dim3 g_dd64(DMODEL / 128, NTOK / 64);    // (8, 128)  64x128 tiles

    // fused QKV projection -> packed fp16 [tok][3072]  (large grid: variant A)
    hgemm<false, false, true><<<g_qkv, 256, HGEMM_SMEM>>>(xh, wqkvh, nullptr, qkvh,
                                                          NTOK, QLD, DMODEL);

    // attention -> fp16 ctx
    flash_attn_h<<<dim3(SEQ / 128, NHEAD, BATCH), 256, AT_SMEM>>>(qkvh, ctxh);

    // output projection -> fp32  (tail-bound shape: variant B)
    hgemm64<false, false, false><<<g_dd64, 256, SGEMM_SMEM>>>(ctxh, woh, nullptr, attn,
                                                              NTOK, DMODEL, DMODEL);

    // add & norm 1 (h fp32 residual, hrh fp16 for FFN1)
    add_ln_kernel<<<NTOK, 256>>>(x, attn, g1, be1, h, hrh);

    // FFN1 (large grid: variant A), FFN2 (tail-bound: variant B)
    hgemm<true, true, true><<<g_df, 256, HGEMM_SMEM>>>(hrh, w1h, b1, ffh,
                                                       NTOK, DFF, DMODEL);
    hgemm64<true, false, false><<<g_dd64, 256, SGEMM_SMEM>>>(ffh, w2h, b2, f2,
                                                             NTOK, DMODEL, DFF);

    // add & norm 2
    add_ln_kernel<<<NTOK, 256>>>(h, f2, g2, be2, out, nullptr);
}